// round 6
// baseline (speedup 1.0000x reference)
#include <cuda_runtime.h>
#include <cstdint>

// ---------------- scratch (no cudaMalloc allowed) ----------------
__device__ float g_qkv[4096 * 3072]; // [B*T, 3*D] fp32
__device__ float g_ctx[4096 * 1024]; // [B*T, D]  tf32-rounded bits
__device__ float g_xa[4096 * 1024];  // x  as tf32 bits
__device__ float g_wa[3072 * 1024];  // w_in  as tf32 bits
__device__ float g_wb[1024 * 1024];  // w_out as tf32 bits

#define LOG2E 1.4426950408889634f

__device__ __forceinline__ float ex2f(float x) {
    float r;
    asm("ex2.approx.ftz.f32 %0, %1;" : "=f"(r) : "f"(x));
    return r;
}

__device__ __forceinline__ uint32_t f2tf(float f) {
    uint32_t r;
    asm("cvt.rna.tf32.f32 %0, %1;" : "=r"(r) : "f"(f));
    return r;
}

__device__ __forceinline__ uint32_t smem_u32(const void* p) {
    uint32_t a;
    asm("{ .reg .u64 t; cvta.to.shared.u64 t, %1; cvt.u32.u64 %0, t; }" : "=r"(a) : "l"(p));
    return a;
}

__device__ __forceinline__ void cp16(uint32_t dst, const void* src) {
    asm volatile("cp.async.cg.shared.global [%0], [%1], 16;" :: "r"(dst), "l"(src));
}

__device__ __forceinline__ void mma_tf32(float* c, const uint32_t* a, const uint32_t* b) {
    asm volatile(
        "mma.sync.aligned.m16n8k8.row.col.f32.tf32.tf32.f32 "
        "{%0,%1,%2,%3}, {%4,%5,%6,%7}, {%8,%9}, {%0,%1,%2,%3};"
        : "+f"(c[0]), "+f"(c[1]), "+f"(c[2]), "+f"(c[3])
        : "r"(a[0]), "r"(a[1]), "r"(a[2]), "r"(a[3]), "r"(b[0]), "r"(b[1]));
}

// ---------------------------------------------------------------------------
// Convert x / w_in / w_out to tf32 bits (round-to-nearest).
// ---------------------------------------------------------------------------
__global__ void __launch_bounds__(256) cvt_tf32(
    const float* __restrict__ x, const float* __restrict__ wi, const float* __restrict__ wo,
    float* __restrict__ xa, float* __restrict__ wa, float* __restrict__ wb)
{
    const int NX = 4096 * 1024 / 4, NI = 3072 * 1024 / 4, NO = 1024 * 1024 / 4;
    int i = blockIdx.x * blockDim.x + threadIdx.x;
    if (i >= NX + NI + NO) return;
    const float4* s;
    float4* d;
    if (i < NX)            { s = (const float4*)x + i;            d = (float4*)xa + i; }
    else if (i < NX + NI)  { s = (const float4*)wi + (i - NX);    d = (float4*)wa + (i - NX); }
    else                   { s = (const float4*)wo + (i - NX - NI); d = (float4*)wb + (i - NX - NI); }
    float4 v = *s;
    float4 o;
    o.x = __uint_as_float(f2tf(v.x));
    o.y = __uint_as_float(f2tf(v.y));
    o.z = __uint_as_float(f2tf(v.z));
    o.w = __uint_as_float(f2tf(v.w));
    *d = o;
}

// ---------------------------------------------------------------------------
// tf32 mma.sync GEMM: C[M,N] = A[M,K] @ B[N,K]^T + bias[N]  (unchanged, R4)
// ---------------------------------------------------------------------------
#define SA_F (256 * 36)
#define SB_F (128 * 36)
#define GEMM_SMEM ((2 * (SA_F + SB_F)) * 4)

__global__ void __launch_bounds__(256) gemm_mma(
    const float* __restrict__ A, const float* __restrict__ B,
    const float* __restrict__ bias, float* __restrict__ C,
    int M, int N, int K)
{
    extern __shared__ float sm[];
    const int AOFF[2] = {0, SA_F + SB_F};
    const int BOFF[2] = {SA_F, 2 * SA_F + SB_F};

    const int tid = threadIdx.x, lane = tid & 31, wid = tid >> 5;
    const int bm = blockIdx.y * 256, bn = blockIdx.x * 128;
    const int m0 = (wid & 3) * 64, n0 = (wid >> 2) * 64;
    const int g = lane >> 2, t = lane & 3;

    float c[4][8][4];
#pragma unroll
    for (int mi = 0; mi < 4; mi++)
#pragma unroll
        for (int ni = 0; ni < 8; ni++)
#pragma unroll
            for (int j = 0; j < 4; j++) c[mi][ni][j] = 0.f;

    const int KT = K >> 5;
    const uint32_t sbase = smem_u32(sm);

    auto issue = [&](int kt, int b) {
        const float* Ag = A + (size_t)bm * K + kt * 32;
        const float* Bg = B + (size_t)bn * K + kt * 32;
        const uint32_t da = sbase + AOFF[b] * 4;
        const uint32_t db = sbase + BOFF[b] * 4;
#pragma unroll
        for (int i = 0; i < 8; i++) {
            const int idx = tid + i * 256;
            const int r = idx >> 3, c4 = idx & 7;
            cp16(da + r * 144 + c4 * 16, Ag + (size_t)r * K + c4 * 4);
        }
#pragma unroll
        for (int i = 0; i < 4; i++) {
            const int idx = tid + i * 256;
            const int r = idx >> 3, c4 = idx & 7;
            cp16(db + r * 144 + c4 * 16, Bg + (size_t)r * K + c4 * 4);
        }
    };

    issue(0, 0);
    asm volatile("cp.async.commit_group;" ::: "memory");

    for (int kt = 0; kt < KT; kt++) {
        const int buf = kt & 1;
        if (kt + 1 < KT) {
            issue(kt + 1, buf ^ 1);
            asm volatile("cp.async.commit_group;" ::: "memory");
            asm volatile("cp.async.wait_group 1;" ::: "memory");
        } else {
            asm volatile("cp.async.wait_group 0;" ::: "memory");
        }
        __syncthreads();

        const float* as = sm + AOFF[buf] + (m0 + g) * 36 + t;
        const float* bs = sm + BOFF[buf] + (n0 + g) * 36 + t;
#pragma unroll
        for (int ks = 0; ks < 4; ks++) {
            const int k = ks * 8;
            uint32_t a[4][4], b[8][2];
#pragma unroll
            for (int mi = 0; mi < 4; mi++) {
                a[mi][0] = __float_as_uint(as[(mi * 16 + 0) * 36 + k]);
                a[mi][1] = __float_as_uint(as[(mi * 16 + 8) * 36 + k]);
                a[mi][2] = __float_as_uint(as[(mi * 16 + 0) * 36 + k + 4]);
                a[mi][3] = __float_as_uint(as[(mi * 16 + 8) * 36 + k + 4]);
            }
#pragma unroll
            for (int ni = 0; ni < 8; ni++) {
                b[ni][0] = __float_as_uint(bs[ni * 8 * 36 + k]);
                b[ni][1] = __float_as_uint(bs[ni * 8 * 36 + k + 4]);
            }
#pragma unroll
            for (int mi = 0; mi < 4; mi++)
#pragma unroll
                for (int ni = 0; ni < 8; ni++)
                    mma_tf32(c[mi][ni], a[mi], b[ni]);
        }
        __syncthreads();
    }

#pragma unroll
    for (int mi = 0; mi < 4; mi++) {
#pragma unroll
        for (int ni = 0; ni < 8; ni++) {
            const int row = bm + m0 + mi * 16 + g;
            const int col = bn + n0 + ni * 8 + t * 2;
            const float2 bb = *(const float2*)(bias + col);
            float2 v0 = make_float2(c[mi][ni][0] + bb.x, c[mi][ni][1] + bb.y);
            float2 v1 = make_float2(c[mi][ni][2] + bb.x, c[mi][ni][3] + bb.y);
            *(float2*)(C + (size_t)row * N + col) = v0;
            *(float2*)(C + (size_t)(row + 8) * N + col) = v1;
        }
    }
}

// ---------------------------------------------------------------------------
// Flash attention (causal), tf32 mma.sync, register-prefetched K/V,
// k-swizzled smem so every fragment load is an LDS.64.
// CTA: 128 q-rows, 256 thr, 8 warps x 16 q-rows. kv-tile 64.
// swz(k) = (k&~7) + ((k&3)<<1) + ((k&4)>>2): MMA pair (t, t+4) -> adjacent.
// Row stride 72 floats: LDS.64 frag loads are bank-conflict-free.
// ---------------------------------------------------------------------------
#define TQ 128
#define AST 72
#define ATTN_SMEM ((128 * AST + 64 * AST + 64 * AST + 128 * AST) * 4)  // 110592 B

__global__ void __launch_bounds__(256) attn_mma(
    const float* __restrict__ qkv, float* __restrict__ ctx)
{
    extern __shared__ float smf[];
    float* Qs = smf;                 // [128][72] swizzled-d, scaled tf32 bits
    float* Ks = smf + 128 * AST;     // [64][72]  row kv, swizzled d
    float* Vt = Ks + 64 * AST;       // [64][72]  row d, swizzled kv
    float* Ps = Vt + 64 * AST;       // [128][72] row q, swizzled kv

    const int tid = threadIdx.x, lane = tid & 31, wid = tid >> 5;
    const int q0 = (int)(gridDim.x - 1 - blockIdx.x) * TQ;  // heavy tiles first
    const int bh = blockIdx.y;
    const int bb = bh >> 4, h = bh & 15;
    const size_t rowbase = (size_t)bb * 2048;
    const int qcol = h * 64, kcol = 1024 + h * 64, vcol = 2048 + h * 64;
    const int g = lane >> 2, t = lane & 3;

    // ---- load Q tile (scaled, tf32, swizzled-d) ----
    {
        const float qs = 0.125f * LOG2E;
        const int rr = tid >> 1, cc = (tid & 1) * 32;
        const float* gq = qkv + (rowbase + q0 + rr) * 3072 + qcol + cc;
        float* sq = Qs + rr * AST + cc;
#pragma unroll
        for (int j = 0; j < 8; j++) {
            float4 v = *(const float4*)(gq + 4 * j);
            const int base = 8 * (j >> 1) + (j & 1);
            sq[base + 0] = __uint_as_float(f2tf(v.x * qs));
            sq[base + 2] = __uint_as_float(f2tf(v.y * qs));
            sq[base + 4] = __uint_as_float(f2tf(v.z * qs));
            sq[base + 6] = __uint_as_float(f2tf(v.w * qs));
        }
    }

    // ---- prefetch kv-tile 0 into registers ----
    const int rK = tid >> 2, cK = (tid & 3) * 16;
    const int swzr = (rK & 0x38) + ((rK & 3) << 1) + ((rK & 4) >> 2);
    float4 kr[4], vr[4];
    {
        const float* gk = qkv + (rowbase + rK) * 3072 + kcol + cK;
        const float* gv = qkv + (rowbase + rK) * 3072 + vcol + cK;
#pragma unroll
        for (int j = 0; j < 4; j++) { kr[j] = *(const float4*)(gk + 4 * j); vr[j] = *(const float4*)(gv + 4 * j); }
    }
    __syncthreads();   // Q stores visible

    // ---- Q A-fragments resident in registers ----
    uint32_t aq[8][4];
    {
        const float* q0p = Qs + (wid * 16 + g) * AST + 2 * t;
        const float* q1p = q0p + 8 * AST;
#pragma unroll
        for (int ks = 0; ks < 8; ks++) {
            float2 v0 = *(const float2*)(q0p + 8 * ks);
            float2 v1 = *(const float2*)(q1p + 8 * ks);
            aq[ks][0] = __float_as_uint(v0.x);
            aq[ks][1] = __float_as_uint(v1.x);
            aq[ks][2] = __float_as_uint(v0.y);
            aq[ks][3] = __float_as_uint(v1.y);
        }
    }

    // ---- store kv-tile 0 (swizzled) ----
    {
#pragma unroll
        for (int j = 0; j < 4; j++) {
            const int base = cK + 8 * (j >> 1) + (j & 1);
            const float* k4 = (const float*)&kr[j];
            const float* v4 = (const float*)&vr[j];
#pragma unroll
            for (int e = 0; e < 4; e++) {
                Ks[rK * AST + base + 2 * e] = __uint_as_float(f2tf(k4[e]));
                Vt[(cK + 4 * j + e) * AST + swzr] = __uint_as_float(f2tf(v4[e]));
            }
        }
    }
    __syncthreads();

    float m0 = -1e30f, m1 = -1e30f, l0 = 0.f, l1 = 0.f;
    float o[8][4];
#pragma unroll
    for (int ni = 0; ni < 8; ni++)
#pragma unroll
        for (int j = 0; j < 4; j++) o[ni][j] = 0.f;

    const int r0 = q0 + wid * 16 + g;
    const int r1 = r0 + 8;
    const int prow = (wid * 16 + g) * AST;
    const int pi0 = (((2 * t) & 3) << 1) | (t >> 1);   // P store idx for col 2t

    const int kend = q0 + 64;
    for (int k0 = 0; k0 <= kend; k0 += 64) {
        // prefetch next tile (overlaps with compute below)
        if (k0 < kend) {
            const float* gk = qkv + (rowbase + k0 + 64 + rK) * 3072 + kcol + cK;
            const float* gv = qkv + (rowbase + k0 + 64 + rK) * 3072 + vcol + cK;
#pragma unroll
            for (int j = 0; j < 4; j++) { kr[j] = *(const float4*)(gk + 4 * j); vr[j] = *(const float4*)(gv + 4 * j); }
        }

        // ---- S = Q K^T ----
        float s[8][4];
#pragma unroll
        for (int ni = 0; ni < 8; ni++)
#pragma unroll
            for (int j = 0; j < 4; j++) s[ni][j] = 0.f;
#pragma unroll
        for (int ni = 0; ni < 8; ni++) {
            const float* bk = Ks + (ni * 8 + g) * AST + 2 * t;
#pragma unroll
            for (int ks = 0; ks < 8; ks++) {
                float2 bv = *(const float2*)(bk + 8 * ks);
                uint32_t bf[2] = {__float_as_uint(bv.x), __float_as_uint(bv.y)};
                mma_tf32(s[ni], aq[ks], bf);
            }
        }

        // ---- causal mask ----
        if (k0 + 64 > q0 + wid * 16) {
#pragma unroll
            for (int ni = 0; ni < 8; ni++) {
                const int col = k0 + ni * 8 + 2 * t;
                if (col > r0)     s[ni][0] = -1e30f;
                if (col + 1 > r0) s[ni][1] = -1e30f;
                if (col > r1)     s[ni][2] = -1e30f;
                if (col + 1 > r1) s[ni][3] = -1e30f;
            }
        }

        // ---- online softmax ----
        float mt0 = -1e30f, mt1 = -1e30f;
#pragma unroll
        for (int ni = 0; ni < 8; ni++) {
            mt0 = fmaxf(mt0, fmaxf(s[ni][0], s[ni][1]));
            mt1 = fmaxf(mt1, fmaxf(s[ni][2], s[ni][3]));
        }
        mt0 = fmaxf(mt0, __shfl_xor_sync(0xffffffffu, mt0, 1));
        mt0 = fmaxf(mt0, __shfl_xor_sync(0xffffffffu, mt0, 2));
        mt1 = fmaxf(mt1, __shfl_xor_sync(0xffffffffu, mt1, 1));
        mt1 = fmaxf(mt1, __shfl_xor_sync(0xffffffffu, mt1, 2));
        const float mn0 = fmaxf(m0, mt0), mn1 = fmaxf(m1, mt1);
        const float cr0 = ex2f(m0 - mn0), cr1 = ex2f(m1 - mn1);
        m0 = mn0; m1 = mn1;

        float ls0 = 0.f, ls1 = 0.f;
#pragma unroll
        for (int ni = 0; ni < 8; ni++) {
            float p0 = ex2f(s[ni][0] - mn0);
            float p1 = ex2f(s[ni][1] - mn0);
            float p2 = ex2f(s[ni][2] - mn1);
            float p3 = ex2f(s[ni][3] - mn1);
            ls0 += p0 + p1;
            ls1 += p2 + p3;
            Ps[prow + 8 * ni + pi0]             = __uint_as_float(f2tf(p0));
            Ps[prow + 8 * ni + pi0 + 2]         = __uint_as_float(f2tf(p1));
            Ps[prow + 8 * AST + 8 * ni + pi0]     = __uint_as_float(f2tf(p2));
            Ps[prow + 8 * AST + 8 * ni + pi0 + 2] = __uint_as_float(f2tf(p3));
        }
        ls0 += __shfl_xor_sync(0xffffffffu, ls0, 1);
        ls0 += __shfl_xor_sync(0xffffffffu, ls0, 2);
        ls1 += __shfl_xor_sync(0xffffffffu, ls1, 1);
        ls1 += __shfl_xor_sync(0xffffffffu, ls1, 2);
        l0 = l0 * cr0 + ls0;
        l1 = l1 * cr1 + ls1;
#pragma unroll
        for (int ni = 0; ni < 8; ni++) {
            o[ni][0] *= cr0; o[ni][1] *= cr0;
            o[ni][2] *= cr1; o[ni][3] *= cr1;
        }

        __syncwarp();   // P strip is warp-private

        // ---- P A-fragments ----
        uint32_t ap[8][4];
        {
            const float* p0p = Ps + prow + 2 * t;
            const float* p1p = p0p + 8 * AST;
#pragma unroll
            for (int ks = 0; ks < 8; ks++) {
                float2 v0 = *(const float2*)(p0p + 8 * ks);
                float2 v1 = *(const float2*)(p1p + 8 * ks);
                ap[ks][0] = __float_as_uint(v0.x);
                ap[ks][1] = __float_as_uint(v1.x);
                ap[ks][2] = __float_as_uint(v0.y);
                ap[ks][3] = __float_as_uint(v1.y);
            }
        }

        // ---- O += P @ V ----
#pragma unroll
        for (int ni = 0; ni < 8; ni++) {
            const float* bv = Vt + (ni * 8 + g) * AST + 2 * t;
#pragma unroll
            for (int ks = 0; ks < 8; ks++) {
                float2 vv = *(const float2*)(bv + 8 * ks);
                uint32_t bf[2] = {__float_as_uint(vv.x), __float_as_uint(vv.y)};
                mma_tf32(o[ni], ap[ks], bf);
            }
        }

        __syncthreads();   // all warps done reading Ks/Vt

        // ---- store prefetched tile ----
        if (k0 < kend) {
#pragma unroll
            for (int j = 0; j < 4; j++) {
                const int base = cK + 8 * (j >> 1) + (j & 1);
                const float* k4 = (const float*)&kr[j];
                const float* v4 = (const float*)&vr[j];
#pragma unroll
                for (int e = 0; e < 4; e++) {
                    Ks[rK * AST + base + 2 * e] = __uint_as_float(f2tf(k4[e]));
                    Vt[(cK + 4 * j + e) * AST + swzr] = __uint_as_float(f2tf(v4[e]));
                }
            }
            __syncthreads();
        }
    }

    // ---- epilogue: normalize, tf32-round (out-proj consumes directly) ----
    const float i0 = 1.f / l0, i1 = 1.f / l1;
#pragma unroll
    for (int ni = 0; ni < 8; ni++) {
        float2 v0, v1;
        v0.x = __uint_as_float(f2tf(o[ni][0] * i0));
        v0.y = __uint_as_float(f2tf(o[ni][1] * i0));
        v1.x = __uint_as_float(f2tf(o[ni][2] * i1));
        v1.y = __uint_as_float(f2tf(o[ni][3] * i1));
        *(float2*)(ctx + (rowbase + r0) * 1024 + h * 64 + ni * 8 + 2 * t) = v0;
        *(float2*)(ctx + (rowbase + r1) * 1024 + h * 64 + ni * 8 + 2 * t) = v1;
    }
}

// ---------------------------------------------------------------------------
extern "C" void kernel_launch(void* const* d_in, const int* in_sizes, int n_in,
                              void* d_out, int out_size)
{
    const float* x     = (const float*)d_in[0];  // [2,2048,1024]
    const float* w_in  = (const float*)d_in[1];  // [3072,1024]
    const float* b_in  = (const float*)d_in[2];  // [3072]
    const float* w_out = (const float*)d_in[3];  // [1024,1024]
    const float* b_out = (const float*)d_in[4];  // [1024]
    float* out = (float*)d_out;                  // [2,2048,1024]

    float *qkv, *ctx, *xa, *wa, *wb;
    cudaGetSymbolAddress((void**)&qkv, g_qkv);
    cudaGetSymbolAddress((void**)&ctx, g_ctx);
    cudaGetSymbolAddress((void**)&xa, g_xa);
    cudaGetSymbolAddress((void**)&wa, g_wa);
    cudaGetSymbolAddress((void**)&wb, g_wb);

    cudaFuncSetAttribute(gemm_mma, cudaFuncAttributeMaxDynamicSharedMemorySize, GEMM_SMEM);
    cudaFuncSetAttribute(attn_mma, cudaFuncAttributeMaxDynamicSharedMemorySize, ATTN_SMEM);

    // 0) round inputs to tf32
    {
        const int n4 = (4096 * 1024 + 3072 * 1024 + 1024 * 1024) / 4;
        cvt_tf32<<<(n4 + 255) / 256, 256>>>(x, w_in, w_out, xa, wa, wb);
    }
    // 1) packed QKV projection: [4096,3072] (tf32 mma.sync)
    {
        dim3 grid(3072 / 128, 4096 / 256);
        gemm_mma<<<grid, 256, GEMM_SMEM>>>(xa, wa, b_in, qkv, 4096, 3072, 1024);
    }
    // 2) causal flash attention -> ctx [4096,1024] (tf32 mma.sync, pipelined)
    {
        dim3 grid(2048 / TQ, 32);
        attn_mma<<<grid, 256, ATTN_SMEM>>>(qkv, ctx);
    }
    // 3) output projection: [4096,1024] (tf32 mma.sync)
    {
        dim3 grid(1024 / 128, 4096 / 256);
        gemm_mma<<<grid, 256, GEMM_SMEM>>>(ctx, wb, b_out, out, 4096, 1024, 1024);
    }
}

// round 7
// speedup vs baseline: 1.0535x; 1.0535x over previous
#include <cuda_runtime.h>
#include <cstdint>

// ---------------- scratch (no cudaMalloc allowed) ----------------
__device__ float g_qkv[4096 * 3072]; // [B*T, 3*D] fp32
__device__ float g_ctx[4096 * 1024]; // [B*T, D]  tf32-rounded bits
__device__ float g_xa[4096 * 1024];  // x  as tf32 bits
__device__ float g_wa[3072 * 1024];  // w_in  as tf32 bits
__device__ float g_wb[1024 * 1024];  // w_out as tf32 bits

#define LOG2E 1.4426950408889634f

__device__ __forceinline__ float ex2f(float x) {
    float r;
    asm("ex2.approx.ftz.f32 %0, %1;" : "=f"(r) : "f"(x));
    return r;
}

__device__ __forceinline__ uint32_t f2tf(float f) {
    uint32_t r;
    asm("cvt.rna.tf32.f32 %0, %1;" : "=r"(r) : "f"(f));
    return r;
}

__device__ __forceinline__ uint32_t smem_u32(const void* p) {
    uint32_t a;
    asm("{ .reg .u64 t; cvta.to.shared.u64 t, %1; cvt.u32.u64 %0, t; }" : "=r"(a) : "l"(p));
    return a;
}

__device__ __forceinline__ void cp16(uint32_t dst, const void* src) {
    asm volatile("cp.async.cg.shared.global [%0], [%1], 16;" :: "r"(dst), "l"(src));
}

__device__ __forceinline__ void mma_tf32(float* c, const uint32_t* a, const uint32_t* b) {
    asm volatile(
        "mma.sync.aligned.m16n8k8.row.col.f32.tf32.tf32.f32 "
        "{%0,%1,%2,%3}, {%4,%5,%6,%7}, {%8,%9}, {%0,%1,%2,%3};"
        : "+f"(c[0]), "+f"(c[1]), "+f"(c[2]), "+f"(c[3])
        : "r"(a[0]), "r"(a[1]), "r"(a[2]), "r"(a[3]), "r"(b[0]), "r"(b[1]));
}

// ---------------------------------------------------------------------------
// Convert x / w_in / w_out to tf32 bits (round-to-nearest).
// ---------------------------------------------------------------------------
__global__ void __launch_bounds__(256) cvt_tf32(
    const float* __restrict__ x, const float* __restrict__ wi, const float* __restrict__ wo,
    float* __restrict__ xa, float* __restrict__ wa, float* __restrict__ wb)
{
    const int NX = 4096 * 1024 / 4, NI = 3072 * 1024 / 4, NO = 1024 * 1024 / 4;
    int i = blockIdx.x * blockDim.x + threadIdx.x;
    if (i >= NX + NI + NO) return;
    const float4* s;
    float4* d;
    if (i < NX)            { s = (const float4*)x + i;            d = (float4*)xa + i; }
    else if (i < NX + NI)  { s = (const float4*)wi + (i - NX);    d = (float4*)wa + (i - NX); }
    else                   { s = (const float4*)wo + (i - NX - NI); d = (float4*)wb + (i - NX - NI); }
    float4 v = *s;
    float4 o;
    o.x = __uint_as_float(f2tf(v.x));
    o.y = __uint_as_float(f2tf(v.y));
    o.z = __uint_as_float(f2tf(v.z));
    o.w = __uint_as_float(f2tf(v.w));
    *d = o;
}

// ---------------------------------------------------------------------------
// tf32 mma.sync GEMM v2: C[M,N] = A[M,K] @ B[N,K]^T + bias[N]
// CTA 256x128, BK=32, 512 threads (16 warps, 4m x 4n, warp tile 64x32).
// 3-stage cp.async pipeline, ONE __syncthreads per k-step.
// Requires M%256==0, N%128==0, K%32==0.
// ---------------------------------------------------------------------------
#define SA_F (256 * 36)
#define SB_F (128 * 36)
#define STAGE_F (SA_F + SB_F)
#define GEMM_SMEM (3 * STAGE_F * 4)    // 165888 B

__global__ void __launch_bounds__(512) gemm_mma(
    const float* __restrict__ A, const float* __restrict__ B,
    const float* __restrict__ bias, float* __restrict__ C,
    int M, int N, int K)
{
    extern __shared__ float sm[];
    const int tid = threadIdx.x, lane = tid & 31, wid = tid >> 5;
    const int bm = blockIdx.y * 256, bn = blockIdx.x * 128;
    const int m0 = (wid & 3) * 64, n0 = (wid >> 2) * 32;
    const int g = lane >> 2, t = lane & 3;

    float c[4][4][4];
#pragma unroll
    for (int mi = 0; mi < 4; mi++)
#pragma unroll
        for (int ni = 0; ni < 4; ni++)
#pragma unroll
            for (int j = 0; j < 4; j++) c[mi][ni][j] = 0.f;

    const int KT = K >> 5;
    const uint32_t sbase = smem_u32(sm);

    auto issue = [&](int kt, int s) {
        const float* Ag = A + (size_t)bm * K + kt * 32;
        const float* Bg = B + (size_t)bn * K + kt * 32;
        const uint32_t da = sbase + (uint32_t)(s * STAGE_F) * 4;
        const uint32_t db = da + SA_F * 4;
#pragma unroll
        for (int i = 0; i < 4; i++) {
            const int idx = tid + i * 512;
            const int r = idx >> 3, c4 = idx & 7;
            cp16(da + r * 144 + c4 * 16, Ag + (size_t)r * K + c4 * 4);
        }
#pragma unroll
        for (int i = 0; i < 2; i++) {
            const int idx = tid + i * 512;
            const int r = idx >> 3, c4 = idx & 7;
            cp16(db + r * 144 + c4 * 16, Bg + (size_t)r * K + c4 * 4);
        }
    };

    issue(0, 0);
    asm volatile("cp.async.commit_group;" ::: "memory");
    issue(1, 1);
    asm volatile("cp.async.commit_group;" ::: "memory");

    int stage = 0;
    for (int kt = 0; kt < KT; kt++) {
        asm volatile("cp.async.wait_group 1;" ::: "memory");
        __syncthreads();
        if (kt + 2 < KT) {
            int ns = stage + 2; if (ns >= 3) ns -= 3;
            issue(kt + 2, ns);
            asm volatile("cp.async.commit_group;" ::: "memory");
        } else {
            // keep group accounting uniform
            asm volatile("cp.async.commit_group;" ::: "memory");
        }

        const float* as = sm + stage * STAGE_F + (m0 + g) * 36 + t;
        const float* bs = sm + stage * STAGE_F + SA_F + (n0 + g) * 36 + t;
#pragma unroll
        for (int ks = 0; ks < 4; ks++) {
            const int k = ks * 8;
            uint32_t a[4][4], b[4][2];
#pragma unroll
            for (int mi = 0; mi < 4; mi++) {
                a[mi][0] = __float_as_uint(as[(mi * 16 + 0) * 36 + k]);
                a[mi][1] = __float_as_uint(as[(mi * 16 + 8) * 36 + k]);
                a[mi][2] = __float_as_uint(as[(mi * 16 + 0) * 36 + k + 4]);
                a[mi][3] = __float_as_uint(as[(mi * 16 + 8) * 36 + k + 4]);
            }
#pragma unroll
            for (int ni = 0; ni < 4; ni++) {
                b[ni][0] = __float_as_uint(bs[ni * 8 * 36 + k]);
                b[ni][1] = __float_as_uint(bs[ni * 8 * 36 + k + 4]);
            }
#pragma unroll
            for (int mi = 0; mi < 4; mi++)
#pragma unroll
                for (int ni = 0; ni < 4; ni++)
                    mma_tf32(c[mi][ni], a[mi], b[ni]);
        }
        if (++stage == 3) stage = 0;
    }

    // epilogue
#pragma unroll
    for (int mi = 0; mi < 4; mi++) {
#pragma unroll
        for (int ni = 0; ni < 4; ni++) {
            const int row = bm + m0 + mi * 16 + g;
            const int col = bn + n0 + ni * 8 + t * 2;
            const float2 bb = *(const float2*)(bias + col);
            float2 v0 = make_float2(c[mi][ni][0] + bb.x, c[mi][ni][1] + bb.y);
            float2 v1 = make_float2(c[mi][ni][2] + bb.x, c[mi][ni][3] + bb.y);
            *(float2*)(C + (size_t)row * N + col) = v0;
            *(float2*)(C + (size_t)(row + 8) * N + col) = v1;
        }
    }
}

// ---------------------------------------------------------------------------
// Flash attention (causal) with tf32 mma.sync for QK^T and PV.  (R5 version)
// CTA: 128 q-rows, 8 warps; warp w owns q-rows [w*16, w*16+16), all 64 cols.
// kv-tile = 64. Smem rows stride 68 (==4 mod 32 -> fragment LDS conflict-free).
// ---------------------------------------------------------------------------
#define TQ 128
#define ATTN_SMEM ((128 * 68 + 64 * 68 + 64 * 68 + 128 * 68) * 4)   // 104448 B

__global__ void __launch_bounds__(256) attn_mma(
    const float* __restrict__ qkv, float* __restrict__ ctx)
{
    extern __shared__ float smf[];
    float* Qs = smf;              // [128][68] tf32 bits (scaled)
    float* Ks = smf + 128 * 68;   // [64][68]  tf32 bits
    float* Vt = Ks + 64 * 68;     // [64][68]  V^T [d][kv], tf32 bits
    float* Ps = Vt + 64 * 68;     // [128][68] P tf32 bits (warp-private strips)

    const int tid = threadIdx.x, lane = tid & 31, wid = tid >> 5;
    const int q0 = (int)(gridDim.x - 1 - blockIdx.x) * TQ;  // heavy tiles first
    const int bh = blockIdx.y;
    const int bb = bh >> 4, h = bh & 15;
    const size_t rowbase = (size_t)bb * 2048;
    const int qcol = h * 64, kcol = 1024 + h * 64, vcol = 2048 + h * 64;
    const int g = lane >> 2, t = lane & 3;

    // ---- load Q tile (scaled by 1/8*log2e, tf32-rounded) ----
    {
        const float qs = 0.125f * LOG2E;
        const int rr = tid >> 1, cc = (tid & 1) * 32;
        const float* gq = qkv + (rowbase + q0 + rr) * 3072 + qcol + cc;
        float* sq = Qs + rr * 68 + cc;
#pragma unroll
        for (int i = 0; i < 32; i += 4) {
            float4 v = *(const float4*)(gq + i);
            float4 w;
            w.x = __uint_as_float(f2tf(v.x * qs));
            w.y = __uint_as_float(f2tf(v.y * qs));
            w.z = __uint_as_float(f2tf(v.z * qs));
            w.w = __uint_as_float(f2tf(v.w * qs));
            *(float4*)(sq + i) = w;
        }
    }

    float m0 = -1e30f, m1 = -1e30f, l0 = 0.f, l1 = 0.f;
    float o[8][4];
#pragma unroll
    for (int ni = 0; ni < 8; ni++)
#pragma unroll
        for (int j = 0; j < 4; j++) o[ni][j] = 0.f;

    const int r0 = q0 + wid * 16 + g;   // rows of c0/c1 and c2/c3
    const int r1 = r0 + 8;
    const int prow = (wid * 16 + g) * 68;

    for (int k0 = 0; k0 <= q0 + 64; k0 += 64) {
        __syncthreads();   // prev tile's Ks/Vt reads done (1st iter: Q stores)
        // ---- load K, V tiles (tf32) ----
        {
            const int rr = tid >> 2, cc = (tid & 3) * 16;
            const float* gk = qkv + (rowbase + k0 + rr) * 3072 + kcol + cc;
            const float* gv = qkv + (rowbase + k0 + rr) * 3072 + vcol + cc;
            float* sk = Ks + rr * 68 + cc;
#pragma unroll
            for (int i = 0; i < 16; i += 4) {
                float4 kv = *(const float4*)(gk + i);
                float4 w;
                w.x = __uint_as_float(f2tf(kv.x));
                w.y = __uint_as_float(f2tf(kv.y));
                w.z = __uint_as_float(f2tf(kv.z));
                w.w = __uint_as_float(f2tf(kv.w));
                *(float4*)(sk + i) = w;
                float4 vv = *(const float4*)(gv + i);
                Vt[(cc + i + 0) * 68 + rr] = __uint_as_float(f2tf(vv.x));
                Vt[(cc + i + 1) * 68 + rr] = __uint_as_float(f2tf(vv.y));
                Vt[(cc + i + 2) * 68 + rr] = __uint_as_float(f2tf(vv.z));
                Vt[(cc + i + 3) * 68 + rr] = __uint_as_float(f2tf(vv.w));
            }
        }
        __syncthreads();

        // ---- S = Q K^T (log2-scaled) ----
        float s[8][4];
#pragma unroll
        for (int ni = 0; ni < 8; ni++)
#pragma unroll
            for (int j = 0; j < 4; j++) s[ni][j] = 0.f;
        {
            const float* aq = Qs + prow + t;
            const float* bk = Ks + g * 68 + t;
#pragma unroll
            for (int ks = 0; ks < 8; ks++) {
                uint32_t a[4];
                a[0] = __float_as_uint(aq[ks * 8]);
                a[1] = __float_as_uint(aq[8 * 68 + ks * 8]);
                a[2] = __float_as_uint(aq[ks * 8 + 4]);
                a[3] = __float_as_uint(aq[8 * 68 + ks * 8 + 4]);
#pragma unroll
                for (int ni = 0; ni < 8; ni++) {
                    uint32_t bf[2];
                    bf[0] = __float_as_uint(bk[ni * 8 * 68 + ks * 8]);
                    bf[1] = __float_as_uint(bk[ni * 8 * 68 + ks * 8 + 4]);
                    mma_tf32(s[ni], a, bf);
                }
            }
        }

        // ---- causal mask (per-warp skip) ----
        if (k0 + 64 > q0 + wid * 16) {
#pragma unroll
            for (int ni = 0; ni < 8; ni++) {
                const int col = k0 + ni * 8 + 2 * t;
                if (col > r0)     s[ni][0] = -1e30f;
                if (col + 1 > r0) s[ni][1] = -1e30f;
                if (col > r1)     s[ni][2] = -1e30f;
                if (col + 1 > r1) s[ni][3] = -1e30f;
            }
        }

        // ---- online softmax (rows r0, r1; quad reduction over t) ----
        float mt0 = -1e30f, mt1 = -1e30f;
#pragma unroll
        for (int ni = 0; ni < 8; ni++) {
            mt0 = fmaxf(mt0, fmaxf(s[ni][0], s[ni][1]));
            mt1 = fmaxf(mt1, fmaxf(s[ni][2], s[ni][3]));
        }
        mt0 = fmaxf(mt0, __shfl_xor_sync(0xffffffffu, mt0, 1));
        mt0 = fmaxf(mt0, __shfl_xor_sync(0xffffffffu, mt0, 2));
        mt1 = fmaxf(mt1, __shfl_xor_sync(0xffffffffu, mt1, 1));
        mt1 = fmaxf(mt1, __shfl_xor_sync(0xffffffffu, mt1, 2));
        const float mn0 = fmaxf(m0, mt0), mn1 = fmaxf(m1, mt1);
        const float cr0 = ex2f(m0 - mn0), cr1 = ex2f(m1 - mn1);
        m0 = mn0; m1 = mn1;

        float ls0 = 0.f, ls1 = 0.f;
#pragma unroll
        for (int ni = 0; ni < 8; ni++) {
            float p0 = ex2f(s[ni][0] - mn0);
            float p1 = ex2f(s[ni][1] - mn0);
            float p2 = ex2f(s[ni][2] - mn1);
            float p3 = ex2f(s[ni][3] - mn1);
            ls0 += p0 + p1;
            ls1 += p2 + p3;
            float2 v0, v1;
            v0.x = __uint_as_float(f2tf(p0));
            v0.y = __uint_as_float(f2tf(p1));
            v1.x = __uint_as_float(f2tf(p2));
            v1.y = __uint_as_float(f2tf(p3));
            *(float2*)(Ps + prow + ni * 8 + 2 * t) = v0;
            *(float2*)(Ps + prow + 8 * 68 + ni * 8 + 2 * t) = v1;
        }
        ls0 += __shfl_xor_sync(0xffffffffu, ls0, 1);
        ls0 += __shfl_xor_sync(0xffffffffu, ls0, 2);
        ls1 += __shfl_xor_sync(0xffffffffu, ls1, 1);
        ls1 += __shfl_xor_sync(0xffffffffu, ls1, 2);
        l0 = l0 * cr0 + ls0;
        l1 = l1 * cr1 + ls1;
#pragma unroll
        for (int ni = 0; ni < 8; ni++) {
            o[ni][0] *= cr0; o[ni][1] *= cr0;
            o[ni][2] *= cr1; o[ni][3] *= cr1;
        }

        __syncwarp();   // P strip is warp-private

        // ---- O += P @ V ----
        {
            const float* ap = Ps + prow + t;
            const float* bv = Vt + g * 68 + t;
#pragma unroll
            for (int ks = 0; ks < 8; ks++) {
                uint32_t a[4];
                a[0] = __float_as_uint(ap[ks * 8]);
                a[1] = __float_as_uint(ap[8 * 68 + ks * 8]);
                a[2] = __float_as_uint(ap[ks * 8 + 4]);
                a[3] = __float_as_uint(ap[8 * 68 + ks * 8 + 4]);
#pragma unroll
                for (int ni = 0; ni < 8; ni++) {
                    uint32_t bf[2];
                    bf[0] = __float_as_uint(bv[ni * 8 * 68 + ks * 8]);
                    bf[1] = __float_as_uint(bv[ni * 8 * 68 + ks * 8 + 4]);
                    mma_tf32(o[ni], a, bf);
                }
            }
        }
        __syncwarp();
    }

    // ---- epilogue: normalize, round to tf32 (out-proj consumes directly) ----
    const float i0 = 1.f / l0, i1 = 1.f / l1;
#pragma unroll
    for (int ni = 0; ni < 8; ni++) {
        float2 v0, v1;
        v0.x = __uint_as_float(f2tf(o[ni][0] * i0));
        v0.y = __uint_as_float(f2tf(o[ni][1] * i0));
        v1.x = __uint_as_float(f2tf(o[ni][2] * i1));
        v1.y = __uint_as_float(f2tf(o[ni][3] * i1));
        *(float2*)(ctx + (rowbase + r0) * 1024 + h * 64 + ni * 8 + 2 * t) = v0;
        *(float2*)(ctx + (rowbase + r1) * 1024 + h * 64 + ni * 8 + 2 * t) = v1;
    }
}

// ---------------------------------------------------------------------------
extern "C" void kernel_launch(void* const* d_in, const int* in_sizes, int n_in,
                              void* d_out, int out_size)
{
    const float* x     = (const float*)d_in[0];  // [2,2048,1024]
    const float* w_in  = (const float*)d_in[1];  // [3072,1024]
    const float* b_in  = (const float*)d_in[2];  // [3072]
    const float* w_out = (const float*)d_in[3];  // [1024,1024]
    const float* b_out = (const float*)d_in[4];  // [1024]
    float* out = (float*)d_out;                  // [2,2048,1024]

    float *qkv, *ctx, *xa, *wa, *wb;
    cudaGetSymbolAddress((void**)&qkv, g_qkv);
    cudaGetSymbolAddress((void**)&ctx, g_ctx);
    cudaGetSymbolAddress((void**)&xa, g_xa);
    cudaGetSymbolAddress((void**)&wa, g_wa);
    cudaGetSymbolAddress((void**)&wb, g_wb);

    cudaFuncSetAttribute(gemm_mma, cudaFuncAttributeMaxDynamicSharedMemorySize, GEMM_SMEM);
    cudaFuncSetAttribute(attn_mma, cudaFuncAttributeMaxDynamicSharedMemorySize, ATTN_SMEM);

    // 0) round inputs to tf32
    {
        const int n4 = (4096 * 1024 + 3072 * 1024 + 1024 * 1024) / 4;
        cvt_tf32<<<(n4 + 255) / 256, 256>>>(x, w_in, w_out, xa, wa, wb);
    }
    // 1) packed QKV projection: [4096,3072] (tf32 mma.sync)
    {
        dim3 grid(3072 / 128, 4096 / 256);
        gemm_mma<<<grid, 512, GEMM_SMEM>>>(xa, wa, b_in, qkv, 4096, 3072, 1024);
    }
    // 2) causal flash attention -> ctx [4096,1024] (tf32 mma.sync)
    {
        dim3 grid(2048 / TQ, 32);
        attn_mma<<<grid, 256, ATTN_SMEM>>>(qkv, ctx);
    }
    // 3) output projection: [4096,1024] (tf32 mma.sync)
    {
        dim3 grid(1024 / 128, 4096 / 256);
        gemm_mma<<<grid, 512, GEMM_SMEM>>>(ctx, wb, b_out, out, 4096, 1024, 1024);
    }
}

// round 8
// speedup vs baseline: 2.2307x; 2.1175x over previous
#include <cuda_runtime.h>
#include <cuda_fp16.h>
#include <cstdint>

// ---------------- scratch (no cudaMalloc allowed) ----------------
__device__ __half g_qkv[4096 * 3072]; // [B*T, 3*D] fp16 (Q part pre-scaled)
__device__ __half g_ctx[4096 * 1024]; // [B*T, D]   fp16
__device__ __half g_xa[4096 * 1024];  // x  fp16
__device__ __half g_wa[3072 * 1024];  // w_in fp16 (rows 0..1023 pre-scaled)
__device__ __half g_wb[1024 * 1024];  // w_out fp16
__device__ float  g_bi[3072];         // b_in (rows 0..1023 pre-scaled)

#define LOG2E 1.4426950408889634f
#define QSCALE (0.125f * LOG2E)

__device__ __forceinline__ float ex2f(float x) {
    float r;
    asm("ex2.approx.ftz.f32 %0, %1;" : "=f"(r) : "f"(x));
    return r;
}

__device__ __forceinline__ uint32_t smem_u32(const void* p) {
    uint32_t a;
    asm("{ .reg .u64 t; cvta.to.shared.u64 t, %1; cvt.u32.u64 %0, t; }" : "=r"(a) : "l"(p));
    return a;
}

__device__ __forceinline__ void cp16(uint32_t dst, const void* src) {
    asm volatile("cp.async.cg.shared.global [%0], [%1], 16;" :: "r"(dst), "l"(src));
}

__device__ __forceinline__ uint32_t ldh2(const __half* p) {
    return *(const uint32_t*)p;
}

__device__ __forceinline__ uint32_t packh2(float lo, float hi) {
    __half2 h = __floats2half2_rn(lo, hi);
    return *(uint32_t*)&h;
}

__device__ __forceinline__ void mma_f16(float* c, const uint32_t* a, uint32_t b0, uint32_t b1) {
    asm volatile(
        "mma.sync.aligned.m16n8k16.row.col.f32.f16.f16.f32 "
        "{%0,%1,%2,%3}, {%4,%5,%6,%7}, {%8,%9}, {%0,%1,%2,%3};"
        : "+f"(c[0]), "+f"(c[1]), "+f"(c[2]), "+f"(c[3])
        : "r"(a[0]), "r"(a[1]), "r"(a[2]), "r"(a[3]), "r"(b0), "r"(b1));
}

__device__ __forceinline__ void ldmx2t(uint32_t& r0, uint32_t& r1, uint32_t addr) {
    asm volatile("ldmatrix.sync.aligned.m8n8.x2.trans.shared.b16 {%0,%1}, [%2];"
                 : "=r"(r0), "=r"(r1) : "r"(addr));
}

// ---------------------------------------------------------------------------
// Convert x / w_in / w_out to fp16; scale w_in q-rows and b_in q-entries.
// ---------------------------------------------------------------------------
__global__ void __launch_bounds__(256) cvt_h(
    const float* __restrict__ x, const float* __restrict__ wi,
    const float* __restrict__ wo, const float* __restrict__ bi,
    __half* __restrict__ xa, __half* __restrict__ wa,
    __half* __restrict__ wb, float* __restrict__ bo)
{
    const int NX = 4096 * 1024 / 4, NI = 3072 * 1024 / 4, NO = 1024 * 1024 / 4;
    const int NB = 3072 / 4;
    int i = blockIdx.x * blockDim.x + threadIdx.x;
    if (i >= NX + NI + NO + NB) return;
    if (i < NX + NI + NO) {
        const float4* s;
        __half* d;
        float sc = 1.f;
        if (i < NX)           { s = (const float4*)x + i;             d = xa + (size_t)i * 4; }
        else if (i < NX + NI) {
            int j = i - NX;
            s = (const float4*)wi + j;
            d = wa + (size_t)j * 4;
            if ((j * 4) >> 10 < 1024) sc = QSCALE;   // q rows of w_in
        } else                { s = (const float4*)wo + (i - NX - NI); d = wb + (size_t)(i - NX - NI) * 4; }
        float4 v = *s;
        __half2 lo = __floats2half2_rn(v.x * sc, v.y * sc);
        __half2 hi = __floats2half2_rn(v.z * sc, v.w * sc);
        *(uint2*)d = make_uint2(*(uint32_t*)&lo, *(uint32_t*)&hi);
    } else {
        int j = (i - NX - NI - NO) * 4;
#pragma unroll
        for (int e = 0; e < 4; e++) {
            float sc = (j + e < 1024) ? QSCALE : 1.f;
            bo[j + e] = bi[j + e] * sc;
        }
    }
}

// ---------------------------------------------------------------------------
// fp16 mma.sync GEMM: C[M,N] = A[M,K] @ B[N,K]^T + bias[N]
// CTA 256x128, BK=32, 512 threads (16 warps, 4m x 4n, warp tile 64x32).
// 3-stage cp.async pipeline. Smem stride 40 halves (conflict-free .b32 frags).
// HALF_OUT: write __half output, else float.
// ---------------------------------------------------------------------------
#define STH 40
#define SA_H (256 * STH)
#define SB_H (128 * STH)
#define STAGE_H (SA_H + SB_H)
#define GEMM_SMEM (3 * STAGE_H * 2)    // 92160 B

template <bool HALF_OUT>
__global__ void __launch_bounds__(512) gemm_h(
    const __half* __restrict__ A, const __half* __restrict__ B,
    const float* __restrict__ bias, void* __restrict__ Cv,
    int M, int N, int K)
{
    extern __shared__ __half smh[];
    const int tid = threadIdx.x, lane = tid & 31, wid = tid >> 5;
    const int bm = blockIdx.y * 256, bn = blockIdx.x * 128;
    const int m0 = (wid & 3) * 64, n0 = (wid >> 2) * 32;
    const int g = lane >> 2, t = lane & 3;

    float c[4][4][4];
#pragma unroll
    for (int mi = 0; mi < 4; mi++)
#pragma unroll
        for (int ni = 0; ni < 4; ni++)
#pragma unroll
            for (int j = 0; j < 4; j++) c[mi][ni][j] = 0.f;

    const int KT = K >> 5;
    const uint32_t sbase = smem_u32(smh);

    auto issue = [&](int kt, int s) {
        const __half* Ag = A + (size_t)bm * K + kt * 32;
        const __half* Bg = B + (size_t)bn * K + kt * 32;
        const uint32_t da = sbase + (uint32_t)(s * STAGE_H) * 2;
        const uint32_t db = da + SA_H * 2;
#pragma unroll
        for (int i = 0; i < 2; i++) {
            const int idx = tid + i * 512;         // 0..1023
            const int r = idx >> 2, c4 = idx & 3;  // 256 rows x 4 16B-chunks
            cp16(da + r * (STH * 2) + c4 * 16, Ag + (size_t)r * K + c4 * 8);
        }
        {
            const int r = tid >> 2, c4 = tid & 3;  // 128 rows x 4 chunks
            cp16(db + r * (STH * 2) + c4 * 16, Bg + (size_t)r * K + c4 * 8);
        }
    };

    issue(0, 0);
    asm volatile("cp.async.commit_group;" ::: "memory");
    issue(1, 1);
    asm volatile("cp.async.commit_group;" ::: "memory");

    int stage = 0;
    for (int kt = 0; kt < KT; kt++) {
        asm volatile("cp.async.wait_group 1;" ::: "memory");
        __syncthreads();
        if (kt + 2 < KT) {
            int ns = stage + 2; if (ns >= 3) ns -= 3;
            issue(kt + 2, ns);
        }
        asm volatile("cp.async.commit_group;" ::: "memory");

        const __half* As = smh + stage * STAGE_H;
        const __half* Bs = As + SA_H;
#pragma unroll
        for (int kg = 0; kg < 2; kg++) {
            const int k = kg * 16 + 2 * t;
            uint32_t a[4][4], b[4][2];
#pragma unroll
            for (int mi = 0; mi < 4; mi++) {
                const __half* ap = As + (m0 + mi * 16 + g) * STH + k;
                a[mi][0] = ldh2(ap);
                a[mi][1] = ldh2(ap + 8 * STH);
                a[mi][2] = ldh2(ap + 8);
                a[mi][3] = ldh2(ap + 8 * STH + 8);
            }
#pragma unroll
            for (int ni = 0; ni < 4; ni++) {
                const __half* bp = Bs + (n0 + ni * 8 + g) * STH + k;
                b[ni][0] = ldh2(bp);
                b[ni][1] = ldh2(bp + 8);
            }
#pragma unroll
            for (int mi = 0; mi < 4; mi++)
#pragma unroll
                for (int ni = 0; ni < 4; ni++)
                    mma_f16(c[mi][ni], a[mi], b[ni][0], b[ni][1]);
        }
        if (++stage == 3) stage = 0;
    }

    // epilogue
#pragma unroll
    for (int mi = 0; mi < 4; mi++) {
#pragma unroll
        for (int ni = 0; ni < 4; ni++) {
            const int row = bm + m0 + mi * 16 + g;
            const int col = bn + n0 + ni * 8 + t * 2;
            const float2 bb = *(const float2*)(bias + col);
            if (HALF_OUT) {
                __half* C = (__half*)Cv;
                __half2 v0 = __floats2half2_rn(c[mi][ni][0] + bb.x, c[mi][ni][1] + bb.y);
                __half2 v1 = __floats2half2_rn(c[mi][ni][2] + bb.x, c[mi][ni][3] + bb.y);
                *(__half2*)(C + (size_t)row * N + col) = v0;
                *(__half2*)(C + (size_t)(row + 8) * N + col) = v1;
            } else {
                float* C = (float*)Cv;
                *(float2*)(C + (size_t)row * N + col) =
                    make_float2(c[mi][ni][0] + bb.x, c[mi][ni][1] + bb.y);
                *(float2*)(C + (size_t)(row + 8) * N + col) =
                    make_float2(c[mi][ni][2] + bb.x, c[mi][ni][3] + bb.y);
            }
        }
    }
}

// ---------------------------------------------------------------------------
// Flash attention (causal), fp16 mma.sync m16n8k16, cp.async double-buffered
// K/V, P kept in registers (C-frag -> A-frag repack), V via ldmatrix.trans.
// CTA: 128 q-rows, 8 warps x 16 rows; kv-tile 64. Smem stride 72 halves.
// ---------------------------------------------------------------------------
#define TQ 128
#define KVH (64 * 72)                      // halves per K or V tile buffer
#define ATTN_SMEM (2 * 2 * KVH * 2)        // 36864 B

__global__ void __launch_bounds__(256) attn_h(
    const __half* __restrict__ qkv, __half* __restrict__ ctx)
{
    extern __shared__ __half smh[];
    // layout: [buf][K|V]: buf0K, buf0V, buf1K, buf1V
    const int tid = threadIdx.x, lane = tid & 31, wid = tid >> 5;
    const int q0 = (int)(gridDim.x - 1 - blockIdx.x) * TQ;
    const int bh = blockIdx.y;
    const int bb = bh >> 4, h = bh & 15;
    const size_t rowbase = (size_t)bb * 2048;
    const int qcol = h * 64, kcol = 1024 + h * 64, vcol = 2048 + h * 64;
    const int g = lane >> 2, t = lane & 3;
    const uint32_t sbase = smem_u32(smh);

    // ---- Q A-fragments straight from gmem (already scaled fp16) ----
    uint32_t aq[4][4];
    {
        const size_t row0 = rowbase + q0 + wid * 16 + g;
#pragma unroll
        for (int kg = 0; kg < 4; kg++) {
            const int col = qcol + kg * 16 + 2 * t;
            aq[kg][0] = ldh2(qkv + row0 * 3072 + col);
            aq[kg][1] = ldh2(qkv + (row0 + 8) * 3072 + col);
            aq[kg][2] = ldh2(qkv + row0 * 3072 + col + 8);
            aq[kg][3] = ldh2(qkv + (row0 + 8) * 3072 + col + 8);
        }
    }

    auto issue_kv = [&](int k0, int buf) {
        const uint32_t kb = sbase + (uint32_t)(buf * 2 * KVH) * 2;
        const uint32_t vb = kb + KVH * 2;
#pragma unroll
        for (int i = 0; i < 2; i++) {
            const int idx = tid + i * 256;       // 0..511
            const int r = idx >> 3, c8 = idx & 7; // 64 rows x 8 16B-chunks
            const size_t grow = (rowbase + k0 + r) * 3072;
            cp16(kb + r * 144 + c8 * 16, qkv + grow + kcol + c8 * 8);
            cp16(vb + r * 144 + c8 * 16, qkv + grow + vcol + c8 * 8);
        }
    };

    float m0 = -1e30f, m1 = -1e30f, l0 = 0.f, l1 = 0.f;
    float o[8][4];
#pragma unroll
    for (int ni = 0; ni < 8; ni++)
#pragma unroll
        for (int j = 0; j < 4; j++) o[ni][j] = 0.f;

    const int r0 = q0 + wid * 16 + g;
    const int r1 = r0 + 8;
    const int kend = q0 + 64;

    issue_kv(0, 0);
    asm volatile("cp.async.commit_group;" ::: "memory");

    for (int k0 = 0; k0 <= kend; k0 += 64) {
        const int buf = (k0 >> 6) & 1;
        if (k0 < kend) {
            issue_kv(k0 + 64, buf ^ 1);
            asm volatile("cp.async.commit_group;" ::: "memory");
            asm volatile("cp.async.wait_group 1;" ::: "memory");
        } else {
            asm volatile("cp.async.wait_group 0;" ::: "memory");
        }
        __syncthreads();

        const __half* Ks = smh + buf * 2 * KVH;
        const uint32_t vbase = sbase + (uint32_t)(buf * 2 * KVH + KVH) * 2;

        // ---- S = Q K^T (log2-scaled) ----
        float s[8][4];
#pragma unroll
        for (int ni = 0; ni < 8; ni++)
#pragma unroll
            for (int j = 0; j < 4; j++) s[ni][j] = 0.f;
#pragma unroll
        for (int ni = 0; ni < 8; ni++) {
            const __half* bp = Ks + (ni * 8 + g) * 72 + 2 * t;
#pragma unroll
            for (int kg = 0; kg < 4; kg++)
                mma_f16(s[ni], aq[kg], ldh2(bp + kg * 16), ldh2(bp + kg * 16 + 8));
        }

        // ---- causal mask ----
        if (k0 + 64 > q0 + wid * 16) {
#pragma unroll
            for (int ni = 0; ni < 8; ni++) {
                const int col = k0 + ni * 8 + 2 * t;
                if (col > r0)     s[ni][0] = -1e30f;
                if (col + 1 > r0) s[ni][1] = -1e30f;
                if (col > r1)     s[ni][2] = -1e30f;
                if (col + 1 > r1) s[ni][3] = -1e30f;
            }
        }

        // ---- online softmax ----
        float mt0 = -1e30f, mt1 = -1e30f;
#pragma unroll
        for (int ni = 0; ni < 8; ni++) {
            mt0 = fmaxf(mt0, fmaxf(s[ni][0], s[ni][1]));
            mt1 = fmaxf(mt1, fmaxf(s[ni][2], s[ni][3]));
        }
        mt0 = fmaxf(mt0, __shfl_xor_sync(0xffffffffu, mt0, 1));
        mt0 = fmaxf(mt0, __shfl_xor_sync(0xffffffffu, mt0, 2));
        mt1 = fmaxf(mt1, __shfl_xor_sync(0xffffffffu, mt1, 1));
        mt1 = fmaxf(mt1, __shfl_xor_sync(0xffffffffu, mt1, 2));
        const float mn0 = fmaxf(m0, mt0), mn1 = fmaxf(m1, mt1);
        const float cr0 = ex2f(m0 - mn0), cr1 = ex2f(m1 - mn1);
        m0 = mn0; m1 = mn1;

        float ls0 = 0.f, ls1 = 0.f;
#pragma unroll
        for (int ni = 0; ni < 8; ni++) {
            s[ni][0] = ex2f(s[ni][0] - mn0);
            s[ni][1] = ex2f(s[ni][1] - mn0);
            s[ni][2] = ex2f(s[ni][2] - mn1);
            s[ni][3] = ex2f(s[ni][3] - mn1);
            ls0 += s[ni][0] + s[ni][1];
            ls1 += s[ni][2] + s[ni][3];
        }
        ls0 += __shfl_xor_sync(0xffffffffu, ls0, 1);
        ls0 += __shfl_xor_sync(0xffffffffu, ls0, 2);
        ls1 += __shfl_xor_sync(0xffffffffu, ls1, 1);
        ls1 += __shfl_xor_sync(0xffffffffu, ls1, 2);
        l0 = l0 * cr0 + ls0;
        l1 = l1 * cr1 + ls1;
#pragma unroll
        for (int ni = 0; ni < 8; ni++) {
            o[ni][0] *= cr0; o[ni][1] *= cr0;
            o[ni][2] *= cr1; o[ni][3] *= cr1;
        }

        // ---- P C-frag -> A-frag repack (registers only) ----
        uint32_t ap[4][4];
#pragma unroll
        for (int kg = 0; kg < 4; kg++) {
            ap[kg][0] = packh2(s[2 * kg][0], s[2 * kg][1]);
            ap[kg][1] = packh2(s[2 * kg][2], s[2 * kg][3]);
            ap[kg][2] = packh2(s[2 * kg + 1][0], s[2 * kg + 1][1]);
            ap[kg][3] = packh2(s[2 * kg + 1][2], s[2 * kg + 1][3]);
        }

        // ---- O += P @ V  (V via ldmatrix.x2.trans from [kv][d] layout) ----
        const int lnm = lane & 15;
#pragma unroll
        for (int ni = 0; ni < 8; ni++) {
#pragma unroll
            for (int kg = 0; kg < 4; kg++) {
                uint32_t b0, b1;
                ldmx2t(b0, b1, vbase + (uint32_t)(((kg * 16 + lnm) * 72 + ni * 8) * 2));
                mma_f16(o[ni], ap[kg], b0, b1);
            }
        }
        __syncthreads();
    }

    // ---- epilogue: normalize, fp16 ----
    const float i0 = 1.f / l0, i1 = 1.f / l1;
#pragma unroll
    for (int ni = 0; ni < 8; ni++) {
        __half2 v0 = __floats2half2_rn(o[ni][0] * i0, o[ni][1] * i0);
        __half2 v1 = __floats2half2_rn(o[ni][2] * i1, o[ni][3] * i1);
        *(__half2*)(ctx + (rowbase + r0) * 1024 + h * 64 + ni * 8 + 2 * t) = v0;
        *(__half2*)(ctx + (rowbase + r1) * 1024 + h * 64 + ni * 8 + 2 * t) = v1;
    }
}

// ---------------------------------------------------------------------------
extern "C" void kernel_launch(void* const* d_in, const int* in_sizes, int n_in,
                              void* d_out, int out_size)
{
    const float* x     = (const float*)d_in[0];  // [2,2048,1024]
    const float* w_in  = (const float*)d_in[1];  // [3072,1024]
    const float* b_in  = (const float*)d_in[2];  // [3072]
    const float* w_out = (const float*)d_in[3];  // [1024,1024]
    const float* b_out = (const float*)d_in[4];  // [1024]
    float* out = (float*)d_out;                  // [2,2048,1024]

    __half *qkv, *ctx, *xa, *wa, *wb;
    float* bi;
    cudaGetSymbolAddress((void**)&qkv, g_qkv);
    cudaGetSymbolAddress((void**)&ctx, g_ctx);
    cudaGetSymbolAddress((void**)&xa, g_xa);
    cudaGetSymbolAddress((void**)&wa, g_wa);
    cudaGetSymbolAddress((void**)&wb, g_wb);
    cudaGetSymbolAddress((void**)&bi, g_bi);

    cudaFuncSetAttribute(gemm_h<true>,  cudaFuncAttributeMaxDynamicSharedMemorySize, GEMM_SMEM);
    cudaFuncSetAttribute(gemm_h<false>, cudaFuncAttributeMaxDynamicSharedMemorySize, GEMM_SMEM);
    cudaFuncSetAttribute(attn_h, cudaFuncAttributeMaxDynamicSharedMemorySize, ATTN_SMEM);

    // 0) convert inputs to fp16 (+ fold Q scale into w_in/b_in)
    {
        const int n = (4096 * 1024 + 3072 * 1024 + 1024 * 1024) / 4 + 3072 / 4;
        cvt_h<<<(n + 255) / 256, 256>>>(x, w_in, w_out, b_in, xa, wa, wb, bi);
    }
    // 1) packed QKV projection -> fp16 qkv
    {
        dim3 grid(3072 / 128, 4096 / 256);
        gemm_h<true><<<grid, 512, GEMM_SMEM>>>(xa, wa, bi, qkv, 4096, 3072, 1024);
    }
    // 2) causal flash attention -> fp16 ctx
    {
        dim3 grid(2048 / TQ, 32);
        attn_h<<<grid, 256, ATTN_SMEM>>>(qkv, ctx);
    }
    // 3) output projection -> fp32 out
    {
        dim3 grid(1024 / 128, 4096 / 256);
        gemm_h<false><<<grid, 512, GEMM_SMEM>>>(ctx, wb, b_out, out, 4096, 1024, 1024);
    }
}

// round 9
// speedup vs baseline: 2.3707x; 1.0628x over previous
#include <cuda_runtime.h>
#include <cuda_fp16.h>
#include <cstdint>

// ---------------- scratch (no cudaMalloc allowed) ----------------
__device__ __half g_qkv[4096 * 3072]; // [B*T, 3*D] fp16 (Q part pre-scaled)
__device__ __half g_ctx[4096 * 1024]; // [B*T, D]   fp16
__device__ __half g_xa[4096 * 1024];  // x  fp16
__device__ __half g_wa[3072 * 1024];  // w_in fp16 (rows 0..1023 pre-scaled)
__device__ __half g_wb[1024 * 1024];  // w_out fp16
__device__ float  g_bi[3072];         // b_in (rows 0..1023 pre-scaled)

#define LOG2E 1.4426950408889634f
#define QSCALE (0.125f * LOG2E)

__device__ __forceinline__ float ex2f(float x) {
    float r;
    asm("ex2.approx.ftz.f32 %0, %1;" : "=f"(r) : "f"(x));
    return r;
}

__device__ __forceinline__ uint32_t smem_u32(const void* p) {
    uint32_t a;
    asm("{ .reg .u64 t; cvta.to.shared.u64 t, %1; cvt.u32.u64 %0, t; }" : "=r"(a) : "l"(p));
    return a;
}

__device__ __forceinline__ void cp16(uint32_t dst, const void* src) {
    asm volatile("cp.async.cg.shared.global [%0], [%1], 16;" :: "r"(dst), "l"(src));
}

__device__ __forceinline__ uint32_t ldh2(const __half* p) {
    return *(const uint32_t*)p;
}

__device__ __forceinline__ uint32_t packh2(float lo, float hi) {
    __half2 h = __floats2half2_rn(lo, hi);
    return *(uint32_t*)&h;
}

__device__ __forceinline__ void mma_f16(float* c, const uint32_t* a, uint32_t b0, uint32_t b1) {
    asm volatile(
        "mma.sync.aligned.m16n8k16.row.col.f32.f16.f16.f32 "
        "{%0,%1,%2,%3}, {%4,%5,%6,%7}, {%8,%9}, {%0,%1,%2,%3};"
        : "+f"(c[0]), "+f"(c[1]), "+f"(c[2]), "+f"(c[3])
        : "r"(a[0]), "r"(a[1]), "r"(a[2]), "r"(a[3]), "r"(b0), "r"(b1));
}

__device__ __forceinline__ void ldmx4(uint32_t& r0, uint32_t& r1, uint32_t& r2, uint32_t& r3,
                                      uint32_t addr) {
    asm volatile("ldmatrix.sync.aligned.m8n8.x4.shared.b16 {%0,%1,%2,%3}, [%4];"
                 : "=r"(r0), "=r"(r1), "=r"(r2), "=r"(r3) : "r"(addr));
}

__device__ __forceinline__ void ldmx2t(uint32_t& r0, uint32_t& r1, uint32_t addr) {
    asm volatile("ldmatrix.sync.aligned.m8n8.x2.trans.shared.b16 {%0,%1}, [%2];"
                 : "=r"(r0), "=r"(r1) : "r"(addr));
}

// ---------------------------------------------------------------------------
// Convert x / w_in / w_out to fp16; scale w_in q-rows and b_in q-entries.
// ---------------------------------------------------------------------------
__global__ void __launch_bounds__(256) cvt_h(
    const float* __restrict__ x, const float* __restrict__ wi,
    const float* __restrict__ wo, const float* __restrict__ bi,
    __half* __restrict__ xa, __half* __restrict__ wa,
    __half* __restrict__ wb, float* __restrict__ bo)
{
    const int NX = 4096 * 1024 / 4, NI = 3072 * 1024 / 4, NO = 1024 * 1024 / 4;
    const int NB = 3072 / 4;
    int i = blockIdx.x * blockDim.x + threadIdx.x;
    if (i >= NX + NI + NO + NB) return;
    if (i < NX + NI + NO) {
        const float4* s;
        __half* d;
        float sc = 1.f;
        if (i < NX)           { s = (const float4*)x + i;             d = xa + (size_t)i * 4; }
        else if (i < NX + NI) {
            int j = i - NX;
            s = (const float4*)wi + j;
            d = wa + (size_t)j * 4;
            if ((j * 4) >> 10 < 1024) sc = QSCALE;   // q rows of w_in
        } else                { s = (const float4*)wo + (i - NX - NI); d = wb + (size_t)(i - NX - NI) * 4; }
        float4 v = *s;
        __half2 lo = __floats2half2_rn(v.x * sc, v.y * sc);
        __half2 hi = __floats2half2_rn(v.z * sc, v.w * sc);
        *(uint2*)d = make_uint2(*(uint32_t*)&lo, *(uint32_t*)&hi);
    } else {
        int j = (i - NX - NI - NO) * 4;
#pragma unroll
        for (int e = 0; e < 4; e++) {
            float sc = (j + e < 1024) ? QSCALE : 1.f;
            bo[j + e] = bi[j + e] * sc;
        }
    }
}

// ---------------------------------------------------------------------------
// fp16 mma.sync GEMM: C[M,N] = A[M,K] @ B[N,K]^T + bias[N]
// CTA 128x128, BK=32, 256 threads (8 warps, 2m x 4n, warp 64x32), 2 CTAs/SM.
// 4-stage cp.async pipeline, ldmatrix.x4 fragment loads.
// ---------------------------------------------------------------------------
#define STH 40
#define SA_H (128 * STH)
#define STAGE_H (2 * SA_H)
#define GEMM_SMEM (4 * STAGE_H * 2)    // 81920 B

template <bool HALF_OUT>
__global__ void __launch_bounds__(256, 2) gemm_h(
    const __half* __restrict__ A, const __half* __restrict__ B,
    const float* __restrict__ bias, void* __restrict__ Cv,
    int M, int N, int K)
{
    extern __shared__ __half smh[];
    const int tid = threadIdx.x, lane = tid & 31, wid = tid >> 5;
    const int bm = blockIdx.y * 128, bn = blockIdx.x * 128;
    const int m0 = (wid & 1) * 64, n0 = (wid >> 1) * 32;
    const int g = lane >> 2, t = lane & 3;

    float c[4][4][4];
#pragma unroll
    for (int mi = 0; mi < 4; mi++)
#pragma unroll
        for (int ni = 0; ni < 4; ni++)
#pragma unroll
            for (int j = 0; j < 4; j++) c[mi][ni][j] = 0.f;

    const int KT = K >> 5;
    const uint32_t sbase = smem_u32(smh);

    auto issue = [&](int kt, int s) {
        const __half* Ag = A + (size_t)bm * K + kt * 32;
        const __half* Bg = B + (size_t)bn * K + kt * 32;
        const uint32_t da = sbase + (uint32_t)(s * STAGE_H) * 2;
        const uint32_t db = da + SA_H * 2;
#pragma unroll
        for (int i = 0; i < 2; i++) {
            const int idx = tid + i * 256;         // 0..511
            const int r = idx >> 2, c4 = idx & 3;  // 128 rows x 4 16B-chunks
            cp16(da + r * (STH * 2) + c4 * 16, Ag + (size_t)r * K + c4 * 8);
            cp16(db + r * (STH * 2) + c4 * 16, Bg + (size_t)r * K + c4 * 8);
        }
    };

    issue(0, 0);
    asm volatile("cp.async.commit_group;" ::: "memory");
    issue(1, 1);
    asm volatile("cp.async.commit_group;" ::: "memory");
    issue(2, 2);
    asm volatile("cp.async.commit_group;" ::: "memory");

    const int lr = lane & 7;           // ldmatrix row-within-tile
    const int j01 = (lane >> 3) & 1;   // tile bit 0
    const int j23 = lane >> 4;         // tile bit 1

    for (int kt = 0; kt < KT; kt++) {
        const int stage = kt & 3;
        asm volatile("cp.async.wait_group 2;" ::: "memory");
        __syncthreads();
        if (kt + 3 < KT) issue(kt + 3, (kt + 3) & 3);
        asm volatile("cp.async.commit_group;" ::: "memory");

        const uint32_t As = sbase + (uint32_t)(stage * STAGE_H) * 2;
        const uint32_t Bs = As + SA_H * 2;
#pragma unroll
        for (int kg = 0; kg < 2; kg++) {
            const int k = kg * 16;
            uint32_t a[4][4], b[4][2];
#pragma unroll
            for (int mi = 0; mi < 4; mi++) {
                // tiles: j0=rows0-7/k0, j1=rows8-15/k0, j2=rows0-7/k8, j3=rows8-15/k8
                uint32_t addr = As + (uint32_t)(((m0 + mi * 16 + j01 * 8 + lr) * STH + k + j23 * 8) * 2);
                ldmx4(a[mi][0], a[mi][1], a[mi][2], a[mi][3], addr);
            }
#pragma unroll
            for (int p = 0; p < 2; p++) {
                // tiles: j0=n0-7/k0, j1=n0-7/k8, j2=n8-15/k0, j3=n8-15/k8
                uint32_t addr = Bs + (uint32_t)(((n0 + p * 16 + j23 * 8 + lr) * STH + k + j01 * 8) * 2);
                ldmx4(b[2 * p][0], b[2 * p][1], b[2 * p + 1][0], b[2 * p + 1][1], addr);
            }
#pragma unroll
            for (int mi = 0; mi < 4; mi++)
#pragma unroll
                for (int ni = 0; ni < 4; ni++)
                    mma_f16(c[mi][ni], a[mi], b[ni][0], b[ni][1]);
        }
    }

    // epilogue
#pragma unroll
    for (int mi = 0; mi < 4; mi++) {
#pragma unroll
        for (int ni = 0; ni < 4; ni++) {
            const int row = bm + m0 + mi * 16 + g;
            const int col = bn + n0 + ni * 8 + t * 2;
            const float2 bb = *(const float2*)(bias + col);
            if (HALF_OUT) {
                __half* C = (__half*)Cv;
                __half2 v0 = __floats2half2_rn(c[mi][ni][0] + bb.x, c[mi][ni][1] + bb.y);
                __half2 v1 = __floats2half2_rn(c[mi][ni][2] + bb.x, c[mi][ni][3] + bb.y);
                *(__half2*)(C + (size_t)row * N + col) = v0;
                *(__half2*)(C + (size_t)(row + 8) * N + col) = v1;
            } else {
                float* C = (float*)Cv;
                *(float2*)(C + (size_t)row * N + col) =
                    make_float2(c[mi][ni][0] + bb.x, c[mi][ni][1] + bb.y);
                *(float2*)(C + (size_t)(row + 8) * N + col) =
                    make_float2(c[mi][ni][2] + bb.x, c[mi][ni][3] + bb.y);
            }
        }
    }
}

// ---------------------------------------------------------------------------
// Flash attention (causal), fp16 mma.sync m16n8k16, cp.async double-buffered
// K/V, P in registers, K via ldmatrix.x4, V via ldmatrix.x2.trans.
// CTA: 128 q-rows, 8 warps x 16 rows; kv-tile 64. Smem stride 72 halves.
// ---------------------------------------------------------------------------
#define TQ 128
#define KVH (64 * 72)                      // halves per K or V tile buffer
#define ATTN_SMEM (2 * 2 * KVH * 2)        // 36864 B

__global__ void __launch_bounds__(256) attn_h(
    const __half* __restrict__ qkv, __half* __restrict__ ctx)
{
    extern __shared__ __half smh[];
    // layout: [buf][K|V]: buf0K, buf0V, buf1K, buf1V
    const int tid = threadIdx.x, lane = tid & 31, wid = tid >> 5;
    const int q0 = (int)(gridDim.x - 1 - blockIdx.x) * TQ;
    const int bh = blockIdx.y;
    const int bb = bh >> 4, h = bh & 15;
    const size_t rowbase = (size_t)bb * 2048;
    const int qcol = h * 64, kcol = 1024 + h * 64, vcol = 2048 + h * 64;
    const int g = lane >> 2, t = lane & 3;
    const uint32_t sbase = smem_u32(smh);

    // ---- Q A-fragments straight from gmem (already scaled fp16) ----
    uint32_t aq[4][4];
    {
        const size_t row0 = rowbase + q0 + wid * 16 + g;
#pragma unroll
        for (int kg = 0; kg < 4; kg++) {
            const int col = qcol + kg * 16 + 2 * t;
            aq[kg][0] = ldh2(qkv + row0 * 3072 + col);
            aq[kg][1] = ldh2(qkv + (row0 + 8) * 3072 + col);
            aq[kg][2] = ldh2(qkv + row0 * 3072 + col + 8);
            aq[kg][3] = ldh2(qkv + (row0 + 8) * 3072 + col + 8);
        }
    }

    auto issue_kv = [&](int k0, int buf) {
        const uint32_t kb = sbase + (uint32_t)(buf * 2 * KVH) * 2;
        const uint32_t vb = kb + KVH * 2;
#pragma unroll
        for (int i = 0; i < 2; i++) {
            const int idx = tid + i * 256;        // 0..511
            const int r = idx >> 3, c8 = idx & 7; // 64 rows x 8 16B-chunks
            const size_t grow = (rowbase + k0 + r) * 3072;
            cp16(kb + r * 144 + c8 * 16, qkv + grow + kcol + c8 * 8);
            cp16(vb + r * 144 + c8 * 16, qkv + grow + vcol + c8 * 8);
        }
    };

    float m0 = -1e30f, m1 = -1e30f, l0 = 0.f, l1 = 0.f;
    float o[8][4];
#pragma unroll
    for (int ni = 0; ni < 8; ni++)
#pragma unroll
        for (int j = 0; j < 4; j++) o[ni][j] = 0.f;

    const int r0 = q0 + wid * 16 + g;
    const int r1 = r0 + 8;
    const int kend = q0 + 64;
    const int lr = lane & 7, jj = lane >> 3;   // ldmatrix x4 decomposition

    issue_kv(0, 0);
    asm volatile("cp.async.commit_group;" ::: "memory");

    for (int k0 = 0; k0 <= kend; k0 += 64) {
        const int buf = (k0 >> 6) & 1;
        if (k0 < kend) {
            issue_kv(k0 + 64, buf ^ 1);
            asm volatile("cp.async.commit_group;" ::: "memory");
            asm volatile("cp.async.wait_group 1;" ::: "memory");
        } else {
            asm volatile("cp.async.wait_group 0;" ::: "memory");
        }
        __syncthreads();

        const uint32_t kbase = sbase + (uint32_t)(buf * 2 * KVH) * 2;
        const uint32_t vbase = kbase + KVH * 2;

        // ---- S = Q K^T (log2-scaled); K frags via ldmatrix.x4 ----
        float s[8][4];
#pragma unroll
        for (int ni = 0; ni < 8; ni++)
#pragma unroll
            for (int j = 0; j < 4; j++) s[ni][j] = 0.f;
#pragma unroll
        for (int ni = 0; ni < 8; ni++) {
            uint32_t bk[8];
            const uint32_t baddr = kbase + (uint32_t)(((ni * 8 + lr) * 72 + jj * 8) * 2);
            ldmx4(bk[0], bk[1], bk[2], bk[3], baddr);        // k 0..31
            ldmx4(bk[4], bk[5], bk[6], bk[7], baddr + 64);   // k 32..63
            mma_f16(s[ni], aq[0], bk[0], bk[1]);
            mma_f16(s[ni], aq[1], bk[2], bk[3]);
            mma_f16(s[ni], aq[2], bk[4], bk[5]);
            mma_f16(s[ni], aq[3], bk[6], bk[7]);
        }

        // ---- causal mask ----
        if (k0 + 64 > q0 + wid * 16) {
#pragma unroll
            for (int ni = 0; ni < 8; ni++) {
                const int col = k0 + ni * 8 + 2 * t;
                if (col > r0)     s[ni][0] = -1e30f;
                if (col + 1 > r0) s[ni][1] = -1e30f;
                if (col > r1)     s[ni][2] = -1e30f;
                if (col + 1 > r1) s[ni][3] = -1e30f;
            }
        }

        // ---- online softmax ----
        float mt0 = -1e30f, mt1 = -1e30f;
#pragma unroll
        for (int ni = 0; ni < 8; ni++) {
            mt0 = fmaxf(mt0, fmaxf(s[ni][0], s[ni][1]));
            mt1 = fmaxf(mt1, fmaxf(s[ni][2], s[ni][3]));
        }
        mt0 = fmaxf(mt0, __shfl_xor_sync(0xffffffffu, mt0, 1));
        mt0 = fmaxf(mt0, __shfl_xor_sync(0xffffffffu, mt0, 2));
        mt1 = fmaxf(mt1, __shfl_xor_sync(0xffffffffu, mt1, 1));
        mt1 = fmaxf(mt1, __shfl_xor_sync(0xffffffffu, mt1, 2));
        const float mn0 = fmaxf(m0, mt0), mn1 = fmaxf(m1, mt1);
        const float cr0 = ex2f(m0 - mn0), cr1 = ex2f(m1 - mn1);
        m0 = mn0; m1 = mn1;

        float ls0 = 0.f, ls1 = 0.f;
#pragma unroll
        for (int ni = 0; ni < 8; ni++) {
            s[ni][0] = ex2f(s[ni][0] - mn0);
            s[ni][1] = ex2f(s[ni][1] - mn0);
            s[ni][2] = ex2f(s[ni][2] - mn1);
            s[ni][3] = ex2f(s[ni][3] - mn1);
            ls0 += s[ni][0] + s[ni][1];
            ls1 += s[ni][2] + s[ni][3];
        }
        ls0 += __shfl_xor_sync(0xffffffffu, ls0, 1);
        ls0 += __shfl_xor_sync(0xffffffffu, ls0, 2);
        ls1 += __shfl_xor_sync(0xffffffffu, ls1, 1);
        ls1 += __shfl_xor_sync(0xffffffffu, ls1, 2);
        l0 = l0 * cr0 + ls0;
        l1 = l1 * cr1 + ls1;
#pragma unroll
        for (int ni = 0; ni < 8; ni++) {
            o[ni][0] *= cr0; o[ni][1] *= cr0;
            o[ni][2] *= cr1; o[ni][3] *= cr1;
        }

        // ---- P C-frag -> A-frag repack (registers only) ----
        uint32_t ap[4][4];
#pragma unroll
        for (int kg = 0; kg < 4; kg++) {
            ap[kg][0] = packh2(s[2 * kg][0], s[2 * kg][1]);
            ap[kg][1] = packh2(s[2 * kg][2], s[2 * kg][3]);
            ap[kg][2] = packh2(s[2 * kg + 1][0], s[2 * kg + 1][1]);
            ap[kg][3] = packh2(s[2 * kg + 1][2], s[2 * kg + 1][3]);
        }

        // ---- O += P @ V  (V via ldmatrix.x2.trans from [kv][d] layout) ----
        const int lnm = lane & 15;
#pragma unroll
        for (int ni = 0; ni < 8; ni++) {
#pragma unroll
            for (int kg = 0; kg < 4; kg++) {
                uint32_t b0, b1;
                ldmx2t(b0, b1, vbase + (uint32_t)(((kg * 16 + lnm) * 72 + ni * 8) * 2));
                mma_f16(o[ni], ap[kg], b0, b1);
            }
        }
        __syncthreads();
    }

    // ---- epilogue: normalize, fp16 ----
    const float i0 = 1.f / l0, i1 = 1.f / l1;
#pragma unroll
    for (int ni = 0; ni < 8; ni++) {
        __half2 v0 = __floats2half2_rn(o[ni][0] * i0, o[ni][1] * i0);
        __half2 v1 = __floats2half2_rn(o[ni][2] * i1, o[ni][3] * i1);
        *(__half2*)(ctx + (rowbase + r0) * 1024 + h * 64 + ni * 8 + 2 * t) = v0;
        *(__half2*)(ctx + (rowbase + r1) * 1024 + h * 64 + ni * 8 + 2 * t) = v1;
    }
}

// ---------------------------------------------------------------------------
extern "C" void kernel_launch(void* const* d_in, const int* in_sizes, int n_in,
                              void* d_out, int out_size)
{
    const float* x     = (const float*)d_in[0];  // [2,2048,1024]
    const float* w_in  = (const float*)d_in[1];  // [3072,1024]
    const float* b_in  = (const float*)d_in[2];  // [3072]
    const float* w_out = (const float*)d_in[3];  // [1024,1024]
    const float* b_out = (const float*)d_in[4];  // [1024]
    float* out = (float*)d_out;                  // [2,2048,1024]

    __half *qkv, *ctx, *xa, *wa, *wb;
    float* bi;
    cudaGetSymbolAddress((void**)&qkv, g_qkv);
    cudaGetSymbolAddress((void**)&ctx, g_ctx);
    cudaGetSymbolAddress((void**)&xa, g_xa);
    cudaGetSymbolAddress((void**)&wa, g_wa);
    cudaGetSymbolAddress((void**)&wb, g_wb);
    cudaGetSymbolAddress((void**)&bi, g_bi);

    cudaFuncSetAttribute(gemm_h<true>,  cudaFuncAttributeMaxDynamicSharedMemorySize, GEMM_SMEM);
    cudaFuncSetAttribute(gemm_h<false>, cudaFuncAttributeMaxDynamicSharedMemorySize, GEMM_SMEM);
    cudaFuncSetAttribute(attn_h, cudaFuncAttributeMaxDynamicSharedMemorySize, ATTN_SMEM);

    // 0) convert inputs to fp16 (+ fold Q scale into w_in/b_in)
    {
        const int n = (4096 * 1024 + 3072 * 1024 + 1024 * 1024) / 4 + 3072 / 4;
        cvt_h<<<(n + 255) / 256, 256>>>(x, w_in, w_out, b_in, xa, wa, wb, bi);
    }
    // 1) packed QKV projection -> fp16 qkv
    {
        dim3 grid(3072 / 128, 4096 / 128);
        gemm_h<true><<<grid, 256, GEMM_SMEM>>>(xa, wa, bi, qkv, 4096, 3072, 1024);
    }
    // 2) causal flash attention -> fp16 ctx
    {
        dim3 grid(2048 / TQ, 32);
        attn_h<<<grid, 256, ATTN_SMEM>>>(qkv, ctx);
    }
    // 3) output projection -> fp32 out
    {
        dim3 grid(1024 / 128, 4096 / 128);
        gemm_h<false><<<grid, 256, GEMM_SMEM>>>(ctx, wb, b_out, out, 4096, 1024, 1024);
    }
}

// round 10
// speedup vs baseline: 2.5644x; 1.0817x over previous
#include <cuda_runtime.h>
#include <cuda_fp16.h>
#include <cstdint>

// ---------------- scratch (no cudaMalloc allowed) ----------------
__device__ __half g_qkv[4096 * 3072]; // [B*T, 3*D] fp16 (Q part pre-scaled)
__device__ __half g_ctx[4096 * 1024]; // [B*T, D]   fp16
__device__ __half g_xa[4096 * 1024];  // x  fp16
__device__ __half g_wa[3072 * 1024];  // w_in fp16 (rows 0..1023 pre-scaled)
__device__ __half g_wb[1024 * 1024];  // w_out fp16
__device__ float  g_bi[3072];         // b_in (rows 0..1023 pre-scaled)

#define LOG2E 1.4426950408889634f
#define QSCALE (0.125f * LOG2E)

__device__ __forceinline__ float ex2f(float x) {
    float r;
    asm("ex2.approx.ftz.f32 %0, %1;" : "=f"(r) : "f"(x));
    return r;
}

__device__ __forceinline__ uint32_t smem_u32(const void* p) {
    uint32_t a;
    asm("{ .reg .u64 t; cvta.to.shared.u64 t, %1; cvt.u32.u64 %0, t; }" : "=r"(a) : "l"(p));
    return a;
}

__device__ __forceinline__ void cp16(uint32_t dst, const void* src) {
    asm volatile("cp.async.cg.shared.global [%0], [%1], 16;" :: "r"(dst), "l"(src));
}

__device__ __forceinline__ uint32_t ldh2(const __half* p) {
    return *(const uint32_t*)p;
}

__device__ __forceinline__ uint32_t packh2(float lo, float hi) {
    __half2 h = __floats2half2_rn(lo, hi);
    return *(uint32_t*)&h;
}

__device__ __forceinline__ void mma_f16(float* c, const uint32_t* a, uint32_t b0, uint32_t b1) {
    asm volatile(
        "mma.sync.aligned.m16n8k16.row.col.f32.f16.f16.f32 "
        "{%0,%1,%2,%3}, {%4,%5,%6,%7}, {%8,%9}, {%0,%1,%2,%3};"
        : "+f"(c[0]), "+f"(c[1]), "+f"(c[2]), "+f"(c[3])
        : "r"(a[0]), "r"(a[1]), "r"(a[2]), "r"(a[3]), "r"(b0), "r"(b1));
}

__device__ __forceinline__ void ldmx4(uint32_t& r0, uint32_t& r1, uint32_t& r2, uint32_t& r3,
                                      uint32_t addr) {
    asm volatile("ldmatrix.sync.aligned.m8n8.x4.shared.b16 {%0,%1,%2,%3}, [%4];"
                 : "=r"(r0), "=r"(r1), "=r"(r2), "=r"(r3) : "r"(addr));
}

__device__ __forceinline__ void ldmx4t(uint32_t& r0, uint32_t& r1, uint32_t& r2, uint32_t& r3,
                                       uint32_t addr) {
    asm volatile("ldmatrix.sync.aligned.m8n8.x4.trans.shared.b16 {%0,%1,%2,%3}, [%4];"
                 : "=r"(r0), "=r"(r1), "=r"(r2), "=r"(r3) : "r"(addr));
}

// ---------------------------------------------------------------------------
// Convert x / w_in / w_out to fp16; scale w_in q-rows and b_in q-entries.
// ---------------------------------------------------------------------------
__global__ void __launch_bounds__(256) cvt_h(
    const float* __restrict__ x, const float* __restrict__ wi,
    const float* __restrict__ wo, const float* __restrict__ bi,
    __half* __restrict__ xa, __half* __restrict__ wa,
    __half* __restrict__ wb, float* __restrict__ bo)
{
    const int NX = 4096 * 1024 / 4, NI = 3072 * 1024 / 4, NO = 1024 * 1024 / 4;
    const int NB = 3072 / 4;
    int i = blockIdx.x * blockDim.x + threadIdx.x;
    if (i >= NX + NI + NO + NB) return;
    if (i < NX + NI + NO) {
        const float4* s;
        __half* d;
        float sc = 1.f;
        if (i < NX)           { s = (const float4*)x + i;             d = xa + (size_t)i * 4; }
        else if (i < NX + NI) {
            int j = i - NX;
            s = (const float4*)wi + j;
            d = wa + (size_t)j * 4;
            if ((j * 4) >> 10 < 1024) sc = QSCALE;   // q rows of w_in
        } else                { s = (const float4*)wo + (i - NX - NI); d = wb + (size_t)(i - NX - NI) * 4; }
        float4 v = *s;
        __half2 lo = __floats2half2_rn(v.x * sc, v.y * sc);
        __half2 hi = __floats2half2_rn(v.z * sc, v.w * sc);
        *(uint2*)d = make_uint2(*(uint32_t*)&lo, *(uint32_t*)&hi);
    } else {
        int j = (i - NX - NI - NO) * 4;
#pragma unroll
        for (int e = 0; e < 4; e++) {
            float sc = (j + e < 1024) ? QSCALE : 1.f;
            bo[j + e] = bi[j + e] * sc;
        }
    }
}

// ---------------------------------------------------------------------------
// fp16 mma.sync GEMM: C[M,N] = A[M,K] @ B[N,K]^T + bias[N]
// CTA 128x128, BK=64, 256 threads (8 warps, 2m x 4n, warp 64x32), 2 CTAs/SM.
// 3-stage cp.async ring, one sync per 64-deep k-step, ldmatrix.x4 frags.
// ---------------------------------------------------------------------------
#define STH 72                      // halves per smem row (64 + 8 pad)
#define SA_H (128 * STH)
#define STAGE_H (2 * SA_H)
#define GEMM_SMEM (3 * STAGE_H * 2) // 110592 B

template <bool HALF_OUT>
__global__ void __launch_bounds__(256, 2) gemm_h(
    const __half* __restrict__ A, const __half* __restrict__ B,
    const float* __restrict__ bias, void* __restrict__ Cv,
    int M, int N, int K)
{
    extern __shared__ __half smh[];
    const int tid = threadIdx.x, lane = tid & 31, wid = tid >> 5;
    const int bm = blockIdx.y * 128, bn = blockIdx.x * 128;
    const int m0 = (wid & 1) * 64, n0 = (wid >> 1) * 32;
    const int g = lane >> 2, t = lane & 3;

    float c[4][4][4];
#pragma unroll
    for (int mi = 0; mi < 4; mi++)
#pragma unroll
        for (int ni = 0; ni < 4; ni++)
#pragma unroll
            for (int j = 0; j < 4; j++) c[mi][ni][j] = 0.f;

    const int KT = K >> 6;   // 64-deep steps
    const uint32_t sbase = smem_u32(smh);

    auto issue = [&](int kt, int s) {
        const __half* Ag = A + (size_t)bm * K + kt * 64;
        const __half* Bg = B + (size_t)bn * K + kt * 64;
        const uint32_t da = sbase + (uint32_t)(s * STAGE_H) * 2;
        const uint32_t db = da + SA_H * 2;
#pragma unroll
        for (int i = 0; i < 4; i++) {
            const int idx = tid + i * 256;         // 0..1023
            const int r = idx >> 3, c8 = idx & 7;  // 128 rows x 8 16B-chunks
            cp16(da + r * (STH * 2) + c8 * 16, Ag + (size_t)r * K + c8 * 8);
            cp16(db + r * (STH * 2) + c8 * 16, Bg + (size_t)r * K + c8 * 8);
        }
    };

    issue(0, 0);
    asm volatile("cp.async.commit_group;" ::: "memory");
    issue(1, 1);
    asm volatile("cp.async.commit_group;" ::: "memory");

    const int lr = lane & 7;           // ldmatrix row-within-tile
    const int j01 = (lane >> 3) & 1;   // tile bit 0
    const int j23 = lane >> 4;         // tile bit 1

    int stage = 0;
    for (int kt = 0; kt < KT; kt++) {
        asm volatile("cp.async.wait_group 1;" ::: "memory");
        __syncthreads();
        if (kt + 2 < KT) {
            int ns = stage + 2; if (ns >= 3) ns -= 3;
            issue(kt + 2, ns);
        }
        asm volatile("cp.async.commit_group;" ::: "memory");

        const uint32_t As = sbase + (uint32_t)(stage * STAGE_H) * 2;
        const uint32_t Bs = As + SA_H * 2;
#pragma unroll
        for (int kg = 0; kg < 4; kg++) {
            const int k = kg * 16;
            uint32_t a[4][4], b[4][2];
#pragma unroll
            for (int mi = 0; mi < 4; mi++) {
                uint32_t addr = As + (uint32_t)(((m0 + mi * 16 + j01 * 8 + lr) * STH + k + j23 * 8) * 2);
                ldmx4(a[mi][0], a[mi][1], a[mi][2], a[mi][3], addr);
            }
#pragma unroll
            for (int p = 0; p < 2; p++) {
                uint32_t addr = Bs + (uint32_t)(((n0 + p * 16 + j23 * 8 + lr) * STH + k + j01 * 8) * 2);
                ldmx4(b[2 * p][0], b[2 * p][1], b[2 * p + 1][0], b[2 * p + 1][1], addr);
            }
#pragma unroll
            for (int mi = 0; mi < 4; mi++)
#pragma unroll
                for (int ni = 0; ni < 4; ni++)
                    mma_f16(c[mi][ni], a[mi], b[ni][0], b[ni][1]);
        }
        if (++stage == 3) stage = 0;
    }

    // epilogue
#pragma unroll
    for (int mi = 0; mi < 4; mi++) {
#pragma unroll
        for (int ni = 0; ni < 4; ni++) {
            const int row = bm + m0 + mi * 16 + g;
            const int col = bn + n0 + ni * 8 + t * 2;
            const float2 bb = *(const float2*)(bias + col);
            if (HALF_OUT) {
                __half* C = (__half*)Cv;
                __half2 v0 = __floats2half2_rn(c[mi][ni][0] + bb.x, c[mi][ni][1] + bb.y);
                __half2 v1 = __floats2half2_rn(c[mi][ni][2] + bb.x, c[mi][ni][3] + bb.y);
                *(__half2*)(C + (size_t)row * N + col) = v0;
                *(__half2*)(C + (size_t)(row + 8) * N + col) = v1;
            } else {
                float* C = (float*)Cv;
                *(float2*)(C + (size_t)row * N + col) =
                    make_float2(c[mi][ni][0] + bb.x, c[mi][ni][1] + bb.y);
                *(float2*)(C + (size_t)(row + 8) * N + col) =
                    make_float2(c[mi][ni][2] + bb.x, c[mi][ni][3] + bb.y);
            }
        }
    }
}

// ---------------------------------------------------------------------------
// Flash attention (causal), fp16 mma.sync m16n8k16, cp.async double-buffered
// K/V, P in registers, K via ldmatrix.x4, V via ldmatrix.x4.trans.
// CTA: 128 q-rows, 8 warps x 16 rows; kv-tile 64. Smem stride 72 halves.
// ---------------------------------------------------------------------------
#define TQ 128
#define KVH (64 * 72)                      // halves per K or V tile buffer
#define ATTN_SMEM (2 * 2 * KVH * 2)        // 36864 B

__global__ void __launch_bounds__(256) attn_h(
    const __half* __restrict__ qkv, __half* __restrict__ ctx)
{
    extern __shared__ __half smh[];
    // layout: [buf][K|V]: buf0K, buf0V, buf1K, buf1V
    const int tid = threadIdx.x, lane = tid & 31, wid = tid >> 5;
    const int q0 = (int)(gridDim.x - 1 - blockIdx.x) * TQ;
    const int bh = blockIdx.y;
    const int bb = bh >> 4, h = bh & 15;
    const size_t rowbase = (size_t)bb * 2048;
    const int qcol = h * 64, kcol = 1024 + h * 64, vcol = 2048 + h * 64;
    const int g = lane >> 2, t = lane & 3;
    const uint32_t sbase = smem_u32(smh);

    // ---- Q A-fragments straight from gmem (already scaled fp16) ----
    uint32_t aq[4][4];
    {
        const size_t row0 = rowbase + q0 + wid * 16 + g;
#pragma unroll
        for (int kg = 0; kg < 4; kg++) {
            const int col = qcol + kg * 16 + 2 * t;
            aq[kg][0] = ldh2(qkv + row0 * 3072 + col);
            aq[kg][1] = ldh2(qkv + (row0 + 8) * 3072 + col);
            aq[kg][2] = ldh2(qkv + row0 * 3072 + col + 8);
            aq[kg][3] = ldh2(qkv + (row0 + 8) * 3072 + col + 8);
        }
    }

    auto issue_kv = [&](int k0, int buf) {
        const uint32_t kb = sbase + (uint32_t)(buf * 2 * KVH) * 2;
        const uint32_t vb = kb + KVH * 2;
#pragma unroll
        for (int i = 0; i < 2; i++) {
            const int idx = tid + i * 256;        // 0..511
            const int r = idx >> 3, c8 = idx & 7; // 64 rows x 8 16B-chunks
            const size_t grow = (rowbase + k0 + r) * 3072;
            cp16(kb + r * 144 + c8 * 16, qkv + grow + kcol + c8 * 8);
            cp16(vb + r * 144 + c8 * 16, qkv + grow + vcol + c8 * 8);
        }
    };

    float m0 = -1e30f, m1 = -1e30f, l0 = 0.f, l1 = 0.f;
    float o[8][4];
#pragma unroll
    for (int ni = 0; ni < 8; ni++)
#pragma unroll
        for (int j = 0; j < 4; j++) o[ni][j] = 0.f;

    const int r0 = q0 + wid * 16 + g;
    const int r1 = r0 + 8;
    const int kend = q0 + 64;
    const int lr = lane & 7, jj = lane >> 3;   // ldmatrix x4 decomposition

    issue_kv(0, 0);
    asm volatile("cp.async.commit_group;" ::: "memory");

    for (int k0 = 0; k0 <= kend; k0 += 64) {
        const int buf = (k0 >> 6) & 1;
        if (k0 < kend) {
            issue_kv(k0 + 64, buf ^ 1);
            asm volatile("cp.async.commit_group;" ::: "memory");
            asm volatile("cp.async.wait_group 1;" ::: "memory");
        } else {
            asm volatile("cp.async.wait_group 0;" ::: "memory");
        }
        __syncthreads();

        const uint32_t kbase = sbase + (uint32_t)(buf * 2 * KVH) * 2;
        const uint32_t vbase = kbase + KVH * 2;

        // ---- S = Q K^T (log2-scaled); K frags via ldmatrix.x4 ----
        float s[8][4];
#pragma unroll
        for (int ni = 0; ni < 8; ni++)
#pragma unroll
            for (int j = 0; j < 4; j++) s[ni][j] = 0.f;
#pragma unroll
        for (int ni = 0; ni < 8; ni++) {
            uint32_t bk[8];
            const uint32_t baddr = kbase + (uint32_t)(((ni * 8 + lr) * 72 + jj * 8) * 2);
            ldmx4(bk[0], bk[1], bk[2], bk[3], baddr);        // k 0..31
            ldmx4(bk[4], bk[5], bk[6], bk[7], baddr + 64);   // k 32..63
            mma_f16(s[ni], aq[0], bk[0], bk[1]);
            mma_f16(s[ni], aq[1], bk[2], bk[3]);
            mma_f16(s[ni], aq[2], bk[4], bk[5]);
            mma_f16(s[ni], aq[3], bk[6], bk[7]);
        }

        // ---- causal mask ----
        if (k0 + 64 > q0 + wid * 16) {
#pragma unroll
            for (int ni = 0; ni < 8; ni++) {
                const int col = k0 + ni * 8 + 2 * t;
                if (col > r0)     s[ni][0] = -1e30f;
                if (col + 1 > r0) s[ni][1] = -1e30f;
                if (col > r1)     s[ni][2] = -1e30f;
                if (col + 1 > r1) s[ni][3] = -1e30f;
            }
        }

        // ---- online softmax ----
        float mt0 = -1e30f, mt1 = -1e30f;
#pragma unroll
        for (int ni = 0; ni < 8; ni++) {
            mt0 = fmaxf(mt0, fmaxf(s[ni][0], s[ni][1]));
            mt1 = fmaxf(mt1, fmaxf(s[ni][2], s[ni][3]));
        }
        mt0 = fmaxf(mt0, __shfl_xor_sync(0xffffffffu, mt0, 1));
        mt0 = fmaxf(mt0, __shfl_xor_sync(0xffffffffu, mt0, 2));
        mt1 = fmaxf(mt1, __shfl_xor_sync(0xffffffffu, mt1, 1));
        mt1 = fmaxf(mt1, __shfl_xor_sync(0xffffffffu, mt1, 2));
        const float mn0 = fmaxf(m0, mt0), mn1 = fmaxf(m1, mt1);
        const float cr0 = ex2f(m0 - mn0), cr1 = ex2f(m1 - mn1);
        m0 = mn0; m1 = mn1;

        float ls0 = 0.f, ls1 = 0.f;
#pragma unroll
        for (int ni = 0; ni < 8; ni++) {
            s[ni][0] = ex2f(s[ni][0] - mn0);
            s[ni][1] = ex2f(s[ni][1] - mn0);
            s[ni][2] = ex2f(s[ni][2] - mn1);
            s[ni][3] = ex2f(s[ni][3] - mn1);
            ls0 += s[ni][0] + s[ni][1];
            ls1 += s[ni][2] + s[ni][3];
        }
        ls0 += __shfl_xor_sync(0xffffffffu, ls0, 1);
        ls0 += __shfl_xor_sync(0xffffffffu, ls0, 2);
        ls1 += __shfl_xor_sync(0xffffffffu, ls1, 1);
        ls1 += __shfl_xor_sync(0xffffffffu, ls1, 2);
        l0 = l0 * cr0 + ls0;
        l1 = l1 * cr1 + ls1;
#pragma unroll
        for (int ni = 0; ni < 8; ni++) {
            o[ni][0] *= cr0; o[ni][1] *= cr0;
            o[ni][2] *= cr1; o[ni][3] *= cr1;
        }

        // ---- P C-frag -> A-frag repack (registers only) ----
        uint32_t ap[4][4];
#pragma unroll
        for (int kg = 0; kg < 4; kg++) {
            ap[kg][0] = packh2(s[2 * kg][0], s[2 * kg][1]);
            ap[kg][1] = packh2(s[2 * kg][2], s[2 * kg][3]);
            ap[kg][2] = packh2(s[2 * kg + 1][0], s[2 * kg + 1][1]);
            ap[kg][3] = packh2(s[2 * kg + 1][2], s[2 * kg + 1][3]);
        }

        // ---- O += P @ V  (V frags via ldmatrix.x4.trans: 2 ni per load) ----
        const int lnm = lane & 15, hf = lane >> 4;
#pragma unroll
        for (int np = 0; np < 4; np++) {
#pragma unroll
            for (int kg = 0; kg < 4; kg++) {
                uint32_t b0, b1, b2, b3;
                ldmx4t(b0, b1, b2, b3,
                       vbase + (uint32_t)(((kg * 16 + lnm) * 72 + np * 16 + hf * 8) * 2));
                mma_f16(o[2 * np],     ap[kg], b0, b1);
                mma_f16(o[2 * np + 1], ap[kg], b2, b3);
            }
        }
        __syncthreads();
    }

    // ---- epilogue: normalize, fp16 ----
    const float i0 = 1.f / l0, i1 = 1.f / l1;
#pragma unroll
    for (int ni = 0; ni < 8; ni++) {
        __half2 v0 = __floats2half2_rn(o[ni][0] * i0, o[ni][1] * i0);
        __half2 v1 = __floats2half2_rn(o[ni][2] * i1, o[ni][3] * i1);
        *(__half2*)(ctx + (rowbase + r0) * 1024 + h * 64 + ni * 8 + 2 * t) = v0;
        *(__half2*)(ctx + (rowbase + r1) * 1024 + h * 64 + ni * 8 + 2 * t) = v1;
    }
}

// ---------------------------------------------------------------------------
extern "C" void kernel_launch(void* const* d_in, const int* in_sizes, int n_in,
                              void* d_out, int out_size)
{
    const float* x     = (const float*)d_in[0];  // [2,2048,1024]
    const float* w_in  = (const float*)d_in[1];  // [3072,1024]
    const float* b_in  = (const float*)d_in[2];  // [3072]
    const float* w_out = (const float*)d_in[3];  // [1024,1024]
    const float* b_out = (const float*)d_in[4];  // [1024]
    float* out = (float*)d_out;                  // [2,2048,1024]

    __half *qkv, *ctx, *xa, *wa, *wb;
    float* bi;
    cudaGetSymbolAddress((void**)&qkv, g_qkv);
    cudaGetSymbolAddress((void**)&ctx, g_ctx);
    cudaGetSymbolAddress((void**)&xa, g_xa);
    cudaGetSymbolAddress((void**)&wa, g_wa);
    cudaGetSymbolAddress((void**)&wb, g_wb);
    cudaGetSymbolAddress((void**)&bi, g_bi);

    cudaFuncSetAttribute(gemm_h<true>,  cudaFuncAttributeMaxDynamicSharedMemorySize, GEMM_SMEM);
    cudaFuncSetAttribute(gemm_h<false>, cudaFuncAttributeMaxDynamicSharedMemorySize, GEMM_SMEM);
    cudaFuncSetAttribute(attn_h, cudaFuncAttributeMaxDynamicSharedMemorySize, ATTN_SMEM);

    // 0) convert inputs to fp16 (+ fold Q scale into w_in/b_in)
    {
        const int n = (4096 * 1024 + 3072 * 1024 + 1024 * 1024) / 4 + 3072 / 4;
        cvt_h<<<(n + 255) / 256, 256>>>(x, w_in, w_out, b_in, xa, wa, wb, bi);
    }
    // 1) packed QKV projection -> fp16 qkv
    {
        dim3 grid(3072 / 128, 4096 / 128);
        gemm_h<true><<<grid, 256, GEMM_SMEM>>>(xa, wa, bi, qkv, 4096, 3072, 1024);
    }
    // 2) causal flash attention -> fp16 ctx
    {
        dim3 grid(2048 / TQ, 32);
        attn_h<<<grid, 256, ATTN_SMEM>>>(qkv, ctx);
    }
    // 3) output projection -> fp32 out
    {
        dim3 grid(1024 / 128, 4096 / 128);
        gemm_h<false><<<grid, 256, GEMM_SMEM>>>(ctx, wb, b_out, out, 4096, 1024, 1024);
    }
}

// round 11
// speedup vs baseline: 2.5906x; 1.0102x over previous
#include <cuda_runtime.h>
#include <cuda_fp16.h>
#include <cstdint>

// ---------------- scratch (no cudaMalloc allowed) ----------------
__device__ __half g_qkv[4096 * 3072]; // [B*T, 3*D] fp16 (Q part pre-scaled)
__device__ __half g_ctx[4096 * 1024]; // [B*T, D]   fp16
__device__ __half g_xa[4096 * 1024];  // x  fp16
__device__ __half g_wa[3072 * 1024];  // w_in fp16 (rows 0..1023 pre-scaled)
__device__ __half g_wb[1024 * 1024];  // w_out fp16
__device__ float  g_bi[3072];         // b_in (rows 0..1023 pre-scaled)

#define LOG2E 1.4426950408889634f
#define QSCALE (0.125f * LOG2E)

__device__ __forceinline__ float ex2f(float x) {
    float r;
    asm("ex2.approx.ftz.f32 %0, %1;" : "=f"(r) : "f"(x));
    return r;
}

__device__ __forceinline__ uint32_t smem_u32(const void* p) {
    uint32_t a;
    asm("{ .reg .u64 t; cvta.to.shared.u64 t, %1; cvt.u32.u64 %0, t; }" : "=r"(a) : "l"(p));
    return a;
}

__device__ __forceinline__ void cp16(uint32_t dst, const void* src) {
    asm volatile("cp.async.cg.shared.global [%0], [%1], 16;" :: "r"(dst), "l"(src));
}

__device__ __forceinline__ uint32_t ldh2(const __half* p) {
    return *(const uint32_t*)p;
}

__device__ __forceinline__ uint32_t packh2(float lo, float hi) {
    __half2 h = __floats2half2_rn(lo, hi);
    return *(uint32_t*)&h;
}

__device__ __forceinline__ void mma_f16(float* c, const uint32_t* a, uint32_t b0, uint32_t b1) {
    asm volatile(
        "mma.sync.aligned.m16n8k16.row.col.f32.f16.f16.f32 "
        "{%0,%1,%2,%3}, {%4,%5,%6,%7}, {%8,%9}, {%0,%1,%2,%3};"
        : "+f"(c[0]), "+f"(c[1]), "+f"(c[2]), "+f"(c[3])
        : "r"(a[0]), "r"(a[1]), "r"(a[2]), "r"(a[3]), "r"(b0), "r"(b1));
}

__device__ __forceinline__ void ldmx4(uint32_t& r0, uint32_t& r1, uint32_t& r2, uint32_t& r3,
                                      uint32_t addr) {
    asm volatile("ldmatrix.sync.aligned.m8n8.x4.shared.b16 {%0,%1,%2,%3}, [%4];"
                 : "=r"(r0), "=r"(r1), "=r"(r2), "=r"(r3) : "r"(addr));
}

__device__ __forceinline__ void ldmx4t(uint32_t& r0, uint32_t& r1, uint32_t& r2, uint32_t& r3,
                                       uint32_t addr) {
    asm volatile("ldmatrix.sync.aligned.m8n8.x4.trans.shared.b16 {%0,%1,%2,%3}, [%4];"
                 : "=r"(r0), "=r"(r1), "=r"(r2), "=r"(r3) : "r"(addr));
}

// ---------------------------------------------------------------------------
// Convert x / w_in / w_out to fp16; scale w_in q-rows and b_in q-entries.
// ---------------------------------------------------------------------------
__global__ void __launch_bounds__(256) cvt_h(
    const float* __restrict__ x, const float* __restrict__ wi,
    const float* __restrict__ wo, const float* __restrict__ bi,
    __half* __restrict__ xa, __half* __restrict__ wa,
    __half* __restrict__ wb, float* __restrict__ bo)
{
    const int NX = 4096 * 1024 / 4, NI = 3072 * 1024 / 4, NO = 1024 * 1024 / 4;
    const int NB = 3072 / 4;
    int i = blockIdx.x * blockDim.x + threadIdx.x;
    if (i >= NX + NI + NO + NB) return;
    if (i < NX + NI + NO) {
        const float4* s;
        __half* d;
        float sc = 1.f;
        if (i < NX)           { s = (const float4*)x + i;             d = xa + (size_t)i * 4; }
        else if (i < NX + NI) {
            int j = i - NX;
            s = (const float4*)wi + j;
            d = wa + (size_t)j * 4;
            if ((j * 4) >> 10 < 1024) sc = QSCALE;   // q rows of w_in
        } else                { s = (const float4*)wo + (i - NX - NI); d = wb + (size_t)(i - NX - NI) * 4; }
        float4 v = *s;
        __half2 lo = __floats2half2_rn(v.x * sc, v.y * sc);
        __half2 hi = __floats2half2_rn(v.z * sc, v.w * sc);
        *(uint2*)d = make_uint2(*(uint32_t*)&lo, *(uint32_t*)&hi);
    } else {
        int j = (i - NX - NI - NO) * 4;
#pragma unroll
        for (int e = 0; e < 4; e++) {
            float sc = (j + e < 1024) ? QSCALE : 1.f;
            bo[j + e] = bi[j + e] * sc;
        }
    }
}

// ---------------------------------------------------------------------------
// fp16 mma.sync GEMM: C[M,N] = A[M,K] @ B[N,K]^T + bias[N]
// CTA 128x128, BK=64, 256 threads (8 warps, 2m x 4n, warp 64x32), 2 CTAs/SM.
// 3-stage cp.async ring, one sync per 64-deep k-step, ldmatrix.x4 frags.
// ---------------------------------------------------------------------------
#define STH 72                      // halves per smem row (64 + 8 pad)
#define SA_H (128 * STH)
#define STAGE_H (2 * SA_H)
#define GEMM_SMEM (3 * STAGE_H * 2) // 110592 B

template <bool HALF_OUT>
__global__ void __launch_bounds__(256, 2) gemm_h(
    const __half* __restrict__ A, const __half* __restrict__ B,
    const float* __restrict__ bias, void* __restrict__ Cv,
    int M, int N, int K)
{
    extern __shared__ __half smh[];
    const int tid = threadIdx.x, lane = tid & 31, wid = tid >> 5;
    const int bm = blockIdx.y * 128, bn = blockIdx.x * 128;
    const int m0 = (wid & 1) * 64, n0 = (wid >> 1) * 32;
    const int g = lane >> 2, t = lane & 3;

    float c[4][4][4];
#pragma unroll
    for (int mi = 0; mi < 4; mi++)
#pragma unroll
        for (int ni = 0; ni < 4; ni++)
#pragma unroll
            for (int j = 0; j < 4; j++) c[mi][ni][j] = 0.f;

    const int KT = K >> 6;   // 64-deep steps
    const uint32_t sbase = smem_u32(smh);

    auto issue = [&](int kt, int s) {
        const __half* Ag = A + (size_t)bm * K + kt * 64;
        const __half* Bg = B + (size_t)bn * K + kt * 64;
        const uint32_t da = sbase + (uint32_t)(s * STAGE_H) * 2;
        const uint32_t db = da + SA_H * 2;
#pragma unroll
        for (int i = 0; i < 4; i++) {
            const int idx = tid + i * 256;         // 0..1023
            const int r = idx >> 3, c8 = idx & 7;  // 128 rows x 8 16B-chunks
            cp16(da + r * (STH * 2) + c8 * 16, Ag + (size_t)r * K + c8 * 8);
            cp16(db + r * (STH * 2) + c8 * 16, Bg + (size_t)r * K + c8 * 8);
        }
    };

    issue(0, 0);
    asm volatile("cp.async.commit_group;" ::: "memory");
    issue(1, 1);
    asm volatile("cp.async.commit_group;" ::: "memory");

    const int lr = lane & 7;           // ldmatrix row-within-tile
    const int j01 = (lane >> 3) & 1;   // tile bit 0
    const int j23 = lane >> 4;         // tile bit 1

    int stage = 0;
    for (int kt = 0; kt < KT; kt++) {
        asm volatile("cp.async.wait_group 1;" ::: "memory");
        __syncthreads();
        if (kt + 2 < KT) {
            int ns = stage + 2; if (ns >= 3) ns -= 3;
            issue(kt + 2, ns);
        }
        asm volatile("cp.async.commit_group;" ::: "memory");

        const uint32_t As = sbase + (uint32_t)(stage * STAGE_H) * 2;
        const uint32_t Bs = As + SA_H * 2;
#pragma unroll
        for (int kg = 0; kg < 4; kg++) {
            const int k = kg * 16;
            uint32_t a[4][4], b[4][2];
#pragma unroll
            for (int mi = 0; mi < 4; mi++) {
                uint32_t addr = As + (uint32_t)(((m0 + mi * 16 + j01 * 8 + lr) * STH + k + j23 * 8) * 2);
                ldmx4(a[mi][0], a[mi][1], a[mi][2], a[mi][3], addr);
            }
#pragma unroll
            for (int p = 0; p < 2; p++) {
                uint32_t addr = Bs + (uint32_t)(((n0 + p * 16 + j23 * 8 + lr) * STH + k + j01 * 8) * 2);
                ldmx4(b[2 * p][0], b[2 * p][1], b[2 * p + 1][0], b[2 * p + 1][1], addr);
            }
#pragma unroll
            for (int mi = 0; mi < 4; mi++)
#pragma unroll
                for (int ni = 0; ni < 4; ni++)
                    mma_f16(c[mi][ni], a[mi], b[ni][0], b[ni][1]);
        }
        if (++stage == 3) stage = 0;
    }

    // epilogue
#pragma unroll
    for (int mi = 0; mi < 4; mi++) {
#pragma unroll
        for (int ni = 0; ni < 4; ni++) {
            const int row = bm + m0 + mi * 16 + g;
            const int col = bn + n0 + ni * 8 + t * 2;
            const float2 bb = *(const float2*)(bias + col);
            if (HALF_OUT) {
                __half* C = (__half*)Cv;
                __half2 v0 = __floats2half2_rn(c[mi][ni][0] + bb.x, c[mi][ni][1] + bb.y);
                __half2 v1 = __floats2half2_rn(c[mi][ni][2] + bb.x, c[mi][ni][3] + bb.y);
                *(__half2*)(C + (size_t)row * N + col) = v0;
                *(__half2*)(C + (size_t)(row + 8) * N + col) = v1;
            } else {
                float* C = (float*)Cv;
                *(float2*)(C + (size_t)row * N + col) =
                    make_float2(c[mi][ni][0] + bb.x, c[mi][ni][1] + bb.y);
                *(float2*)(C + (size_t)(row + 8) * N + col) =
                    make_float2(c[mi][ni][2] + bb.x, c[mi][ni][3] + bb.y);
            }
        }
    }
}

// ---------------------------------------------------------------------------
// Flash attention (causal), fp16 mma.sync m16n8k16, cp.async double-buffered
// K/V, P in registers, K via ldmatrix.x4, V via ldmatrix.x4.trans.
// CTA: 128 q-rows, 8 warps x 16 rows; kv-tile 64. 2 CTAs/SM co-resident.
// ---------------------------------------------------------------------------
#define TQ 128
#define KVH (64 * 72)                      // halves per K or V tile buffer
#define ATTN_SMEM (2 * 2 * KVH * 2)        // 36864 B

__global__ void __launch_bounds__(256, 2) attn_h(
    const __half* __restrict__ qkv, __half* __restrict__ ctx)
{
    extern __shared__ __half smh[];
    // layout: [buf][K|V]: buf0K, buf0V, buf1K, buf1V
    const int tid = threadIdx.x, lane = tid & 31, wid = tid >> 5;
    const int q0 = (int)(gridDim.x - 1 - blockIdx.x) * TQ;
    const int bh = blockIdx.y;
    const int bb = bh >> 4, h = bh & 15;
    const size_t rowbase = (size_t)bb * 2048;
    const int qcol = h * 64, kcol = 1024 + h * 64, vcol = 2048 + h * 64;
    const int g = lane >> 2, t = lane & 3;
    const uint32_t sbase = smem_u32(smh);

    // ---- Q A-fragments straight from gmem (already scaled fp16) ----
    uint32_t aq[4][4];
    {
        const size_t row0 = rowbase + q0 + wid * 16 + g;
#pragma unroll
        for (int kg = 0; kg < 4; kg++) {
            const int col = qcol + kg * 16 + 2 * t;
            aq[kg][0] = ldh2(qkv + row0 * 3072 + col);
            aq[kg][1] = ldh2(qkv + (row0 + 8) * 3072 + col);
            aq[kg][2] = ldh2(qkv + row0 * 3072 + col + 8);
            aq[kg][3] = ldh2(qkv + (row0 + 8) * 3072 + col + 8);
        }
    }

    auto issue_kv = [&](int k0, int buf) {
        const uint32_t kb = sbase + (uint32_t)(buf * 2 * KVH) * 2;
        const uint32_t vb = kb + KVH * 2;
#pragma unroll
        for (int i = 0; i < 2; i++) {
            const int idx = tid + i * 256;        // 0..511
            const int r = idx >> 3, c8 = idx & 7; // 64 rows x 8 16B-chunks
            const size_t grow = (rowbase + k0 + r) * 3072;
            cp16(kb + r * 144 + c8 * 16, qkv + grow + kcol + c8 * 8);
            cp16(vb + r * 144 + c8 * 16, qkv + grow + vcol + c8 * 8);
        }
    };

    float m0 = -1e30f, m1 = -1e30f, l0 = 0.f, l1 = 0.f;
    float o[8][4];
#pragma unroll
    for (int ni = 0; ni < 8; ni++)
#pragma unroll
        for (int j = 0; j < 4; j++) o[ni][j] = 0.f;

    const int r0 = q0 + wid * 16 + g;
    const int r1 = r0 + 8;
    const int kend = q0 + 64;
    const int lr = lane & 7, jj = lane >> 3;   // ldmatrix x4 decomposition

    issue_kv(0, 0);
    asm volatile("cp.async.commit_group;" ::: "memory");

    for (int k0 = 0; k0 <= kend; k0 += 64) {
        const int buf = (k0 >> 6) & 1;
        if (k0 < kend) {
            issue_kv(k0 + 64, buf ^ 1);
            asm volatile("cp.async.commit_group;" ::: "memory");
            asm volatile("cp.async.wait_group 1;" ::: "memory");
        } else {
            asm volatile("cp.async.wait_group 0;" ::: "memory");
        }
        __syncthreads();

        const uint32_t kbase = sbase + (uint32_t)(buf * 2 * KVH) * 2;
        const uint32_t vbase = kbase + KVH * 2;

        // ---- S = Q K^T (log2-scaled); K frags via ldmatrix.x4 ----
        float s[8][4];
#pragma unroll
        for (int ni = 0; ni < 8; ni++)
#pragma unroll
            for (int j = 0; j < 4; j++) s[ni][j] = 0.f;
#pragma unroll
        for (int ni = 0; ni < 8; ni++) {
            uint32_t bk[8];
            const uint32_t baddr = kbase + (uint32_t)(((ni * 8 + lr) * 72 + jj * 8) * 2);
            ldmx4(bk[0], bk[1], bk[2], bk[3], baddr);        // k 0..31
            ldmx4(bk[4], bk[5], bk[6], bk[7], baddr + 64);   // k 32..63
            mma_f16(s[ni], aq[0], bk[0], bk[1]);
            mma_f16(s[ni], aq[1], bk[2], bk[3]);
            mma_f16(s[ni], aq[2], bk[4], bk[5]);
            mma_f16(s[ni], aq[3], bk[6], bk[7]);
        }

        // ---- causal mask ----
        if (k0 + 64 > q0 + wid * 16) {
#pragma unroll
            for (int ni = 0; ni < 8; ni++) {
                const int col = k0 + ni * 8 + 2 * t;
                if (col > r0)     s[ni][0] = -1e30f;
                if (col + 1 > r0) s[ni][1] = -1e30f;
                if (col > r1)     s[ni][2] = -1e30f;
                if (col + 1 > r1) s[ni][3] = -1e30f;
            }
        }

        // ---- online softmax ----
        float mt0 = -1e30f, mt1 = -1e30f;
#pragma unroll
        for (int ni = 0; ni < 8; ni++) {
            mt0 = fmaxf(mt0, fmaxf(s[ni][0], s[ni][1]));
            mt1 = fmaxf(mt1, fmaxf(s[ni][2], s[ni][3]));
        }
        mt0 = fmaxf(mt0, __shfl_xor_sync(0xffffffffu, mt0, 1));
        mt0 = fmaxf(mt0, __shfl_xor_sync(0xffffffffu, mt0, 2));
        mt1 = fmaxf(mt1, __shfl_xor_sync(0xffffffffu, mt1, 1));
        mt1 = fmaxf(mt1, __shfl_xor_sync(0xffffffffu, mt1, 2));
        const float mn0 = fmaxf(m0, mt0), mn1 = fmaxf(m1, mt1);
        const float cr0 = ex2f(m0 - mn0), cr1 = ex2f(m1 - mn1);
        m0 = mn0; m1 = mn1;

        float ls0 = 0.f, ls1 = 0.f;
#pragma unroll
        for (int ni = 0; ni < 8; ni++) {
            s[ni][0] = ex2f(s[ni][0] - mn0);
            s[ni][1] = ex2f(s[ni][1] - mn0);
            s[ni][2] = ex2f(s[ni][2] - mn1);
            s[ni][3] = ex2f(s[ni][3] - mn1);
            ls0 += s[ni][0] + s[ni][1];
            ls1 += s[ni][2] + s[ni][3];
        }
        ls0 += __shfl_xor_sync(0xffffffffu, ls0, 1);
        ls0 += __shfl_xor_sync(0xffffffffu, ls0, 2);
        ls1 += __shfl_xor_sync(0xffffffffu, ls1, 1);
        ls1 += __shfl_xor_sync(0xffffffffu, ls1, 2);
        l0 = l0 * cr0 + ls0;
        l1 = l1 * cr1 + ls1;
#pragma unroll
        for (int ni = 0; ni < 8; ni++) {
            o[ni][0] *= cr0; o[ni][1] *= cr0;
            o[ni][2] *= cr1; o[ni][3] *= cr1;
        }

        // ---- P C-frag -> A-frag repack (registers only) ----
        uint32_t ap[4][4];
#pragma unroll
        for (int kg = 0; kg < 4; kg++) {
            ap[kg][0] = packh2(s[2 * kg][0], s[2 * kg][1]);
            ap[kg][1] = packh2(s[2 * kg][2], s[2 * kg][3]);
            ap[kg][2] = packh2(s[2 * kg + 1][0], s[2 * kg + 1][1]);
            ap[kg][3] = packh2(s[2 * kg + 1][2], s[2 * kg + 1][3]);
        }

        // ---- O += P @ V  (V frags via ldmatrix.x4.trans: 2 ni per load) ----
        const int lnm = lane & 15, hf = lane >> 4;
#pragma unroll
        for (int np = 0; np < 4; np++) {
#pragma unroll
            for (int kg = 0; kg < 4; kg++) {
                uint32_t b0, b1, b2, b3;
                ldmx4t(b0, b1, b2, b3,
                       vbase + (uint32_t)(((kg * 16 + lnm) * 72 + np * 16 + hf * 8) * 2));
                mma_f16(o[2 * np],     ap[kg], b0, b1);
                mma_f16(o[2 * np + 1], ap[kg], b2, b3);
            }
        }
        __syncthreads();
    }

    // ---- epilogue: normalize, fp16 ----
    const float i0 = 1.f / l0, i1 = 1.f / l1;
#pragma unroll
    for (int ni = 0; ni < 8; ni++) {
        __half2 v0 = __floats2half2_rn(o[ni][0] * i0, o[ni][1] * i0);
        __half2 v1 = __floats2half2_rn(o[ni][2] * i1, o[ni][3] * i1);
        *(__half2*)(ctx + (rowbase + r0) * 1024 + h * 64 + ni * 8 + 2 * t) = v0;
        *(__half2*)(ctx + (rowbase + r1) * 1024 + h * 64 + ni * 8 + 2 * t) = v1;
    }
}

// ---------------------------------------------------------------------------
extern "C" void kernel_launch(void* const* d_in, const int* in_sizes, int n_in,
                              void* d_out, int out_size)
{
    const float* x     = (const float*)d_in[0];  // [2,2048,1024]
    const float* w_in  = (const float*)d_in[1];  // [3072,1024]
    const float* b_in  = (const float*)d_in[2];  // [3072]
    const float* w_out = (const float*)d_in[3];  // [1024,1024]
    const float* b_out = (const float*)d_in[4];  // [1024]
    float* out = (float*)d_out;                  // [2,2048,1024]

    __half *qkv, *ctx, *xa, *wa, *wb;
    float* bi;
    cudaGetSymbolAddress((void**)&qkv, g_qkv);
    cudaGetSymbolAddress((void**)&ctx, g_ctx);
    cudaGetSymbolAddress((void**)&xa, g_xa);
    cudaGetSymbolAddress((void**)&wa, g_wa);
    cudaGetSymbolAddress((void**)&wb, g_wb);
    cudaGetSymbolAddress((void**)&bi, g_bi);

    cudaFuncSetAttribute(gemm_h<true>,  cudaFuncAttributeMaxDynamicSharedMemorySize, GEMM_SMEM);
    cudaFuncSetAttribute(gemm_h<false>, cudaFuncAttributeMaxDynamicSharedMemorySize, GEMM_SMEM);
    cudaFuncSetAttribute(attn_h, cudaFuncAttributeMaxDynamicSharedMemorySize, ATTN_SMEM);

    // 0) convert inputs to fp16 (+ fold Q scale into w_in/b_in)
    {
        const int n = (4096 * 1024 + 3072 * 1024 + 1024 * 1024) / 4 + 3072 / 4;
        cvt_h<<<(n + 255) / 256, 256>>>(x, w_in, w_out, b_in, xa, wa, wb, bi);
    }
    // 1) packed QKV projection -> fp16 qkv
    {
        dim3 grid(3072 / 128, 4096 / 128);
        gemm_h<true><<<grid, 256, GEMM_SMEM>>>(xa, wa, bi, qkv, 4096, 3072, 1024);
    }
    // 2) causal flash attention -> fp16 ctx (2 CTAs/SM)
    {
        dim3 grid(2048 / TQ, 32);
        attn_h<<<grid, 256, ATTN_SMEM>>>(qkv, ctx);
    }
    // 3) output projection -> fp32 out
    {
        dim3 grid(1024 / 128, 4096 / 128);
        gemm_h<false><<<grid, 256, GEMM_SMEM>>>(ctx, wb, b_out, out, 4096, 1024, 1024);
    }
}